// round 2
// baseline (speedup 1.0000x reference)
#include <cuda_runtime.h>
#include <math.h>
#include <stdint.h>

#define BB 16
#define LL 128
#define HH 20
#define GG 80
#define MR (BB*LL)
#define KSPL 8
#define KP1 27808
#define S3OFF1 896
#define KP2 8432
#define S3OFF2 432

__device__ __align__(256) float g_a[MR*32];
__device__ __align__(256) float g_X1[(size_t)MR*KP1];
__device__ __align__(256) float g_X2[(size_t)MR*KP2];
__device__ float g_mean[KP1];
__device__ float g_invstd[KP1];
__device__ __align__(256) float g_Wr[(size_t)GG*KP1];
__device__ float g_pb[GG];
__device__ float g_xproj[MR*GG];
__device__ float g_part[KSPL*MR*GG];
__device__ float g_o[MR*HH];

__global__ void augment_kernel(const float* __restrict__ inp,
                               const float* __restrict__ w1, const float* __restrict__ b1,
                               const float* __restrict__ w2, const float* __restrict__ b2) {
    int bl = blockIdx.x;
    int l = bl & (LL-1);
    int tid = threadIdx.x; // 64
    __shared__ float xin[20], hid[64], out8[8];
    if (tid < 20) xin[tid] = inp[bl*20 + tid];
    __syncthreads();
    {
        float a = b1[tid];
        const float* wr = w1 + tid*20;
        #pragma unroll
        for (int c = 0; c < 20; c++) a = fmaf(wr[c], xin[c], a);
        hid[tid] = fmaxf(a, 0.f);
    }
    __syncthreads();
    if (tid < 8) {
        float a = b2[tid];
        const float* wr = w2 + tid*64;
        #pragma unroll 8
        for (int c = 0; c < 64; c++) a = fmaf(wr[c], hid[c], a);
        out8[tid] = a;
    }
    __syncthreads();
    if (tid < 32) {
        float v = 0.f;
        if (tid == 0) v = (float)l * (1.0f/127.0f);
        else if (tid < 21) v = xin[tid-1];
        else if (tid < 29) v = out8[tid-21];
        g_a[bl*32 + tid] = v;
    }
}

// depth-3 streamed signature; thread p=(i,j) owns s2[i,j] (reg) and s3[i,j,:] (regs)
template<int C, int RUN, int S3OFF, int KP>
__global__ void __launch_bounds__(896) sig_kernel(const float* __restrict__ in, int instride,
                                                  float* __restrict__ X) {
    const int CP = C*C;
    int b = blockIdx.x, tid = threadIdx.x;
    __shared__ __align__(16) float d[32];
    __shared__ float s1[32], prev[32];
    if (tid < 32) { d[tid] = 0.f; s1[tid] = 0.f; prev[tid] = 0.f; }
    float s2r = 0.f;
    float s3r[RUN];
    #pragma unroll
    for (int q = 0; q < RUN; q++) s3r[q] = 0.f;
    int i = tid / C, j = tid - i*C;
    bool act = tid < CP;
    __syncthreads();
    for (int t = 0; t < LL; t++) {
        if (tid < 32) {
            float cur = (tid < C) ? in[(b*LL + t)*instride + tid] : 0.f;
            d[tid] = cur - prev[tid];
            prev[tid] = cur;
        }
        __syncthreads();
        float* Xr = X + (size_t)(b*LL + t)*KP;
        if (act) {
            float di = d[i], dj = d[j], s1i = s1[i];
            float gam = fmaf(dj, fmaf(di, (1.f/6.f), 0.5f*s1i), s2r);
            s2r = fmaf(dj, fmaf(0.5f, di, s1i), s2r);
            const float4* d4 = (const float4*)d;
            float4* o4 = (float4*)(Xr + S3OFF + tid*RUN);
            #pragma unroll
            for (int q = 0; q < RUN/4; q++) {
                float4 dq = d4[q];
                s3r[4*q+0] = fmaf(gam, dq.x, s3r[4*q+0]);
                s3r[4*q+1] = fmaf(gam, dq.y, s3r[4*q+1]);
                s3r[4*q+2] = fmaf(gam, dq.z, s3r[4*q+2]);
                s3r[4*q+3] = fmaf(gam, dq.w, s3r[4*q+3]);
                o4[q] = make_float4(s3r[4*q+0], s3r[4*q+1], s3r[4*q+2], s3r[4*q+3]);
            }
            Xr[32 + tid] = s2r;
        }
        __syncthreads();
        if (tid < C) s1[tid] += d[tid];
        if (tid < 32) Xr[tid] = (tid < C) ? s1[tid] : 0.f;
    }
}

__global__ void stats_kernel(const float* __restrict__ X, int KP) {
    int c = blockIdx.x*128 + threadIdx.x;
    if (c >= KP) return;
    const float* p = X + c;
    double sd = 0.0, qd = 0.0;
    for (int r = 0; r < MR; r += 8) {
        float v0 = p[(size_t)(r+0)*KP], v1 = p[(size_t)(r+1)*KP];
        float v2 = p[(size_t)(r+2)*KP], v3 = p[(size_t)(r+3)*KP];
        float v4 = p[(size_t)(r+4)*KP], v5 = p[(size_t)(r+5)*KP];
        float v6 = p[(size_t)(r+6)*KP], v7 = p[(size_t)(r+7)*KP];
        sd += (double)(((v0+v1)+(v2+v3)) + ((v4+v5)+(v6+v7)));
        qd += (double)(((v0*v0+v1*v1)+(v2*v2+v3*v3)) + ((v4*v4+v5*v5)+(v6*v6+v7*v7)));
    }
    double m = sd * (1.0/2048.0);
    double var = qd * (1.0/2048.0) - m*m;
    g_mean[c] = (float)m;
    g_invstd[c] = (float)(1.0 / sqrt(var + 1e-5));
}

template<int C, int S3OFF, int RUN, int KP>
__global__ void wfold_kernel(const float* __restrict__ W) {
    int idx = blockIdx.x*256 + threadIdx.x;
    if (idx >= GG*KP) return;
    int g = idx / KP, cp = idx - g*KP;
    const int CP = C*C;
    int c = -1;
    if (cp < 32) { if (cp < C) c = cp; }
    else if (cp < 32 + CP) c = C + (cp - 32);
    else if (cp >= S3OFF) {
        int r = cp - S3OFF; int p = r / RUN; int k = r - p*RUN;
        if (k < C) c = C + CP + p*C + k;
    }
    float v = 0.f;
    if (c >= 0) v = W[(size_t)g*(C + CP + CP*C) + c] * g_invstd[cp];
    g_Wr[idx] = v;
}

__global__ void projbias_kernel(const float* __restrict__ bih, const float* __restrict__ bhh, int KP) {
    int g = blockIdx.x, tid = threadIdx.x;
    __shared__ double red[256];
    double s = 0.0;
    for (int c = tid; c < KP; c += 256)
        s += (double)g_Wr[(size_t)g*KP + c] * (double)g_mean[c];
    red[tid] = s; __syncthreads();
    for (int st = 128; st > 0; st >>= 1) { if (tid < st) red[tid] += red[tid+st]; __syncthreads(); }
    if (tid == 0) g_pb[g] = bih[g] + bhh[g] - (float)red[0];
}

// X(2048 x KP) * Wr^T -> partials; tile M=128, N=80, K-split over blockIdx.y
__global__ void __launch_bounds__(256) gemm_kernel(const float* __restrict__ X, int KP, int KC) {
    __shared__ __align__(16) float As[128*32];
    __shared__ float Bs[80*33];
    int m0 = blockIdx.x * 128;
    int ks = blockIdx.y;
    int k0 = ks * KC;
    int kend = min(k0 + KC, KP);
    int tid = threadIdx.x;
    int tx = tid & 15, ty = tid >> 4;
    float acc[8][5];
    #pragma unroll
    for (int a = 0; a < 8; a++)
        #pragma unroll
        for (int bq = 0; bq < 5; bq++) acc[a][bq] = 0.f;
    for (int kb = k0; kb < kend; kb += 32) {
        #pragma unroll
        for (int u = 0; u < 4; u++) {
            int f4 = tid + u*256;           // 0..1023
            int row = f4 >> 3, kq = f4 & 7;
            int kg = kb + kq*4;
            float4 v = make_float4(0.f,0.f,0.f,0.f);
            if (kg < KP) v = *(const float4*)(X + (size_t)(m0 + row)*KP + kg);
            *(float4*)(As + row*32 + kq*4) = v;
        }
        #pragma unroll
        for (int u = 0; u < 10; u++) {
            int idx = tid + u*256;
            int row = idx >> 5, kk = idx & 31;
            int kg = kb + kk;
            Bs[row*33 + kk] = (kg < KP) ? g_Wr[(size_t)row*KP + kg] : 0.f;
        }
        __syncthreads();
        #pragma unroll
        for (int kk = 0; kk < 32; kk++) {
            float av[8], bv[5];
            #pragma unroll
            for (int ii = 0; ii < 8; ii++) av[ii] = As[(ty*8 + ii)*32 + kk];
            #pragma unroll
            for (int jj = 0; jj < 5; jj++) bv[jj] = Bs[(tx*5 + jj)*33 + kk];
            #pragma unroll
            for (int ii = 0; ii < 8; ii++)
                #pragma unroll
                for (int jj = 0; jj < 5; jj++)
                    acc[ii][jj] = fmaf(av[ii], bv[jj], acc[ii][jj]);
        }
        __syncthreads();
    }
    float* P = g_part + (size_t)ks*MR*GG;
    #pragma unroll
    for (int ii = 0; ii < 8; ii++)
        #pragma unroll
        for (int jj = 0; jj < 5; jj++)
            P[(m0 + ty*8 + ii)*GG + tx*5 + jj] = acc[ii][jj];
}

__global__ void reduce_kernel() {
    int idx = blockIdx.x*256 + threadIdx.x;
    if (idx >= MR*GG) return;
    float s = g_pb[idx % GG];
    #pragma unroll
    for (int ks = 0; ks < KSPL; ks++) s += g_part[ks*MR*GG + idx];
    g_xproj[idx] = s;
}

__device__ __forceinline__ float sigf(float x) { return 1.f / (1.f + __expf(-x)); }

__global__ void lstm2_kernel(const float* __restrict__ whh0,
                             const float* __restrict__ wih1, const float* __restrict__ whh1,
                             const float* __restrict__ bih1, const float* __restrict__ bhh1) {
    int b = blockIdx.x, tid = threadIdx.x;   // 96 threads
    __shared__ float h[20], gs[80], h0seq[LL*20];
    float w0r[20], w1i[20], w1h[20];
    float bias1 = 0.f;
    if (tid < 80) {
        #pragma unroll
        for (int jj = 0; jj < 20; jj++) {
            w0r[jj] = whh0[tid*20 + jj];
            w1i[jj] = wih1[tid*20 + jj];
            w1h[jj] = whh1[tid*20 + jj];
        }
        bias1 = bih1[tid] + bhh1[tid];
    }
    float cj = 0.f;
    if (tid < 20) h[tid] = 0.f;
    __syncthreads();
    for (int t = 0; t < LL; t++) {          // layer 0
        if (tid < 80) {
            float g = g_xproj[(b*LL + t)*GG + tid];
            #pragma unroll
            for (int jj = 0; jj < 20; jj++) g = fmaf(w0r[jj], h[jj], g);
            gs[tid] = (tid >= 40 && tid < 60) ? tanhf(g) : sigf(g);
        }
        __syncthreads();
        if (tid < 20) {
            cj = fmaf(gs[20+tid], cj, gs[tid]*gs[40+tid]);
            float hj = gs[60+tid] * tanhf(cj);
            h[tid] = hj;
            h0seq[t*20 + tid] = hj;
        }
        __syncthreads();
    }
    cj = 0.f;
    if (tid < 20) h[tid] = 0.f;
    __syncthreads();
    for (int t = 0; t < LL; t++) {          // layer 1
        if (tid < 80) {
            float g = bias1;
            const float* xi = h0seq + t*20;
            #pragma unroll
            for (int jj = 0; jj < 20; jj++) g = fmaf(w1i[jj], xi[jj], g);
            #pragma unroll
            for (int jj = 0; jj < 20; jj++) g = fmaf(w1h[jj], h[jj], g);
            gs[tid] = (tid >= 40 && tid < 60) ? tanhf(g) : sigf(g);
        }
        __syncthreads();
        if (tid < 20) {
            cj = fmaf(gs[20+tid], cj, gs[tid]*gs[40+tid]);
            float hj = gs[60+tid] * tanhf(cj);
            h[tid] = hj;
            g_o[(b*LL + t)*HH + tid] = hj;
        }
        __syncthreads();
    }
}

__global__ void final_kernel(const float* __restrict__ lw, const float* __restrict__ lb,
                             float* __restrict__ out) {
    int r = blockIdx.x*256 + threadIdx.x;
    if (r >= MR) return;
    float s = lb[0];
    #pragma unroll
    for (int hh = 0; hh < HH; hh++) {
        float v = g_o[r*HH + hh];
        v = (v >= 0.f) ? v : 0.01f*v;
        s = fmaf(v, lw[hh], s);
    }
    out[r] = s;
}

static void run_stage(const float* X, int KP, int KC,
                      const float* wih0, const float* whh0,
                      const float* bih0, const float* bhh0,
                      const float* wih1, const float* whh1,
                      const float* bih1, const float* bhh1,
                      bool first) {
    stats_kernel<<<(KP + 127)/128, 128>>>(X, KP);
    if (first)
        wfold_kernel<29, S3OFF1, 32, KP1><<<(GG*KP1 + 255)/256, 256>>>(wih0);
    else
        wfold_kernel<20, S3OFF2, 20, KP2><<<(GG*KP2 + 255)/256, 256>>>(wih0);
    projbias_kernel<<<GG, 256>>>(bih0, bhh0, KP);
    gemm_kernel<<<dim3(MR/128, KSPL), 256>>>(X, KP, KC);
    reduce_kernel<<<(MR*GG + 255)/256, 256>>>();
    lstm2_kernel<<<BB, 96>>>(whh0, wih1, whh1, bih1, bhh1);
}

extern "C" void kernel_launch(void* const* d_in, const int* in_sizes, int n_in,
                              void* d_out, int out_size) {
    const float* inp = (const float*)d_in[0];
    const float* aw1 = (const float*)d_in[1];
    const float* ab1 = (const float*)d_in[2];
    const float* aw2 = (const float*)d_in[3];
    const float* ab2 = (const float*)d_in[4];
    const float* p[24];
    for (int i = 0; i < 24; i++) p[i] = (const float*)d_in[5 + i];
    const float* lin_w = (const float*)d_in[29];
    const float* lin_b = (const float*)d_in[30];
    float* out = (float*)d_out;

    float* ga;  cudaGetSymbolAddress((void**)&ga,  g_a);
    float* gx1; cudaGetSymbolAddress((void**)&gx1, g_X1);
    float* gx2; cudaGetSymbolAddress((void**)&gx2, g_X2);
    float* go;  cudaGetSymbolAddress((void**)&go,  g_o);

    augment_kernel<<<MR, 64>>>(inp, aw1, ab1, aw2, ab2);
    sig_kernel<29, 32, S3OFF1, KP1><<<BB, 896>>>(ga, 32, gx1);
    run_stage(gx1, KP1, 3488, p[0], p[1], p[2], p[3], p[4], p[5], p[6], p[7], true);
    sig_kernel<20, 20, S3OFF2, KP2><<<BB, 416>>>(go, HH, gx2);
    run_stage(gx2, KP2, 1056, p[8], p[9], p[10], p[11], p[12], p[13], p[14], p[15], false);
    sig_kernel<20, 20, S3OFF2, KP2><<<BB, 416>>>(go, HH, gx2);
    run_stage(gx2, KP2, 1056, p[16], p[17], p[18], p[19], p[20], p[21], p[22], p[23], false);
    final_kernel<<<(MR + 255)/256, 256>>>(lin_w, lin_b, out);
}

// round 3
// speedup vs baseline: 2.0052x; 2.0052x over previous
#include <cuda_runtime.h>
#include <math.h>
#include <stdint.h>

#define BB 16
#define LL 128
#define HH 20
#define GG 80
#define MR (BB*LL)
#define KSPL 32
#define KP1 27808
#define S3OFF1 896
#define KP2 8432
#define S3OFF2 432

__device__ __align__(256) float g_a[MR*32];
__device__ __align__(256) float g_X1[(size_t)MR*KP1];
__device__ __align__(256) float g_X2[(size_t)MR*KP2];
__device__ float g_mean[KP1];
__device__ float g_invstd[KP1];
__device__ __align__(256) float g_Wr[(size_t)GG*KP1];
__device__ float g_pb[GG];
__device__ float g_xproj[MR*GG];
__device__ float g_part[(size_t)KSPL*MR*GG];
__device__ float g_o[MR*HH];

// ---------- f32x2 helpers ----------
__device__ __forceinline__ unsigned long long pack2(float lo, float hi) {
    unsigned long long r;
    asm("mov.b64 %0, {%1, %2};" : "=l"(r) : "f"(lo), "f"(hi));
    return r;
}
__device__ __forceinline__ void fma2(unsigned long long& acc, unsigned long long a, unsigned long long b) {
    asm("fma.rn.f32x2 %0, %1, %2, %0;" : "+l"(acc) : "l"(a), "l"(b));
}
__device__ __forceinline__ void unpack2(unsigned long long v, float& lo, float& hi) {
    asm("mov.b64 {%0, %1}, %2;" : "=f"(lo), "=f"(hi) : "l"(v));
}

__global__ void augment_kernel(const float* __restrict__ inp,
                               const float* __restrict__ w1, const float* __restrict__ b1,
                               const float* __restrict__ w2, const float* __restrict__ b2) {
    int bl = blockIdx.x;
    int l = bl & (LL-1);
    int tid = threadIdx.x; // 64
    __shared__ float xin[20], hid[64], out8[8];
    if (tid < 20) xin[tid] = inp[bl*20 + tid];
    __syncthreads();
    {
        float a = b1[tid];
        const float* wr = w1 + tid*20;
        #pragma unroll
        for (int c = 0; c < 20; c++) a = fmaf(wr[c], xin[c], a);
        hid[tid] = fmaxf(a, 0.f);
    }
    __syncthreads();
    if (tid < 8) {
        float a = b2[tid];
        const float* wr = w2 + tid*64;
        #pragma unroll 8
        for (int c = 0; c < 64; c++) a = fmaf(wr[c], hid[c], a);
        out8[tid] = a;
    }
    __syncthreads();
    if (tid < 32) {
        float v = 0.f;
        if (tid == 0) v = (float)l * (1.0f/127.0f);
        else if (tid < 21) v = xin[tid-1];
        else if (tid < 29) v = out8[tid-21];
        g_a[bl*32 + tid] = v;
    }
}

// streamed depth-3 signature, split over pair-row groups.
// grid: (NSPLIT, BB). Each CTA redundantly maintains d/s1; owns pairs with
// i in [g*C/NSPLIT, (g+1)*C/NSPLIT).
template<int C, int RUN, int S3OFF, int KP, int NSPLIT>
__global__ void sig_kernel(const float* __restrict__ in, int instride,
                           float* __restrict__ X) {
    int g = blockIdx.x, b = blockIdx.y;
    int i0 = (g*C)/NSPLIT, i1 = ((g+1)*C)/NSPLIT;
    int tid = threadIdx.x;
    __shared__ __align__(16) float d[32];
    __shared__ float s1[32];
    int np = (i1 - i0) * C;
    bool act = tid < np;
    int i = i0 + tid / C, j = tid % C;
    int pg = i*C + j;                       // global pair index
    float s2r = 0.f;
    float s3r[RUN];
    #pragma unroll
    for (int q = 0; q < RUN; q++) s3r[q] = 0.f;
    float prev = 0.f;
    if (tid < 32) { d[tid] = 0.f; s1[tid] = 0.f; }
    float nxt = (tid < C) ? in[(b*LL)*instride + tid] : 0.f;
    __syncthreads();
    for (int t = 0; t < LL; t++) {
        if (tid < 32) {
            float cur = (tid < C) ? nxt : 0.f;
            d[tid] = cur - prev;
            prev = cur;
        }
        __syncthreads();
        if (tid < C && t+1 < LL) nxt = in[(b*LL + t+1)*instride + tid];
        float* Xr = X + (size_t)(b*LL + t)*KP;
        if (act) {
            float di = d[i], dj = d[j], s1i = s1[i];
            float gam = fmaf(dj, fmaf(di, (1.f/6.f), 0.5f*s1i), s2r);
            s2r = fmaf(dj, fmaf(0.5f, di, s1i), s2r);
            const float4* d4 = (const float4*)d;
            float4* o4 = (float4*)(Xr + S3OFF + pg*RUN);
            #pragma unroll
            for (int q = 0; q < RUN/4; q++) {
                float4 dq = d4[q];
                s3r[4*q+0] = fmaf(gam, dq.x, s3r[4*q+0]);
                s3r[4*q+1] = fmaf(gam, dq.y, s3r[4*q+1]);
                s3r[4*q+2] = fmaf(gam, dq.z, s3r[4*q+2]);
                s3r[4*q+3] = fmaf(gam, dq.w, s3r[4*q+3]);
                o4[q] = make_float4(s3r[4*q+0], s3r[4*q+1], s3r[4*q+2], s3r[4*q+3]);
            }
            Xr[32 + pg] = s2r;
        }
        __syncthreads();
        if (tid < C) s1[tid] += d[tid];
        if (g == 0) {
            if (tid < 32) Xr[tid] = (tid < C) ? s1[tid] : 0.f;
            int gap0 = 32 + C*C;
            if (gap0 + tid < S3OFF) Xr[gap0 + tid] = 0.f;   // zero pad gap (C=29)
        }
    }
}

__global__ void stats_kernel(const float* __restrict__ X, int KP) {
    int c = blockIdx.x*128 + threadIdx.x;
    if (c >= KP) return;
    const float* p = X + c;
    double sd = 0.0, qd = 0.0;
    for (int r = 0; r < MR; r += 8) {
        float v0 = p[(size_t)(r+0)*KP], v1 = p[(size_t)(r+1)*KP];
        float v2 = p[(size_t)(r+2)*KP], v3 = p[(size_t)(r+3)*KP];
        float v4 = p[(size_t)(r+4)*KP], v5 = p[(size_t)(r+5)*KP];
        float v6 = p[(size_t)(r+6)*KP], v7 = p[(size_t)(r+7)*KP];
        sd += (double)(((v0+v1)+(v2+v3)) + ((v4+v5)+(v6+v7)));
        qd += (double)(((v0*v0+v1*v1)+(v2*v2+v3*v3)) + ((v4*v4+v5*v5)+(v6*v6+v7*v7)));
    }
    double m = sd * (1.0/2048.0);
    double var = qd * (1.0/2048.0) - m*m;
    g_mean[c] = (float)m;
    g_invstd[c] = (float)(1.0 / sqrt(var + 1e-5));
}

template<int C, int S3OFF, int RUN, int KP>
__global__ void wfold_kernel(const float* __restrict__ W) {
    int idx = blockIdx.x*256 + threadIdx.x;
    if (idx >= GG*KP) return;
    int g = idx / KP, cp = idx - g*KP;
    const int CP = C*C;
    int c = -1;
    if (cp < 32) { if (cp < C) c = cp; }
    else if (cp < 32 + CP) c = C + (cp - 32);
    else if (cp >= S3OFF) {
        int r = cp - S3OFF; int p = r / RUN; int k = r - p*RUN;
        if (k < C) c = C + CP + p*C + k;
    }
    float v = 0.f;
    if (c >= 0) v = W[(size_t)g*(C + CP + CP*C) + c] * g_invstd[cp];
    g_Wr[idx] = v;
}

__global__ void projbias_kernel(const float* __restrict__ bih, const float* __restrict__ bhh, int KP) {
    int g = blockIdx.x, tid = threadIdx.x;
    __shared__ double red[256];
    double s = 0.0;
    for (int c = tid; c < KP; c += 256)
        s += (double)g_Wr[(size_t)g*KP + c] * (double)g_mean[c];
    red[tid] = s; __syncthreads();
    for (int st = 128; st > 0; st >>= 1) { if (tid < st) red[tid] += red[tid+st]; __syncthreads(); }
    if (tid == 0) g_pb[g] = bih[g] + bhh[g] - (float)red[0];
}

// X(2048 x KP) * Wr^T -> partials; tile M=128, N=80, K-split over blockIdx.y
__global__ void __launch_bounds__(256) gemm_kernel(const float* __restrict__ X, int KP, int KC) {
    __shared__ __align__(16) float As[128*32];
    __shared__ float Bs[80*33];
    int m0 = blockIdx.x * 128;
    int ks = blockIdx.y;
    int k0 = ks * KC;
    int kend = min(k0 + KC, KP);
    int tid = threadIdx.x;
    int tx = tid & 15, ty = tid >> 4;
    unsigned long long acc2[4][5];
    #pragma unroll
    for (int a = 0; a < 4; a++)
        #pragma unroll
        for (int bq = 0; bq < 5; bq++) acc2[a][bq] = 0ull;
    for (int kb = k0; kb < kend; kb += 32) {
        #pragma unroll
        for (int u = 0; u < 4; u++) {
            int f4 = tid + u*256;
            int row = f4 >> 3, kq = f4 & 7;
            int kg = kb + kq*4;
            float4 v = make_float4(0.f,0.f,0.f,0.f);
            if (kg < KP) v = *(const float4*)(X + (size_t)(m0 + row)*KP + kg);
            *(float4*)(As + row*32 + kq*4) = v;
        }
        #pragma unroll
        for (int u = 0; u < 10; u++) {
            int idx = tid + u*256;
            int row = idx >> 5, kk = idx & 31;
            int kg = kb + kk;
            Bs[row*33 + kk] = (kg < KP) ? g_Wr[(size_t)row*KP + kg] : 0.f;
        }
        __syncthreads();
        #pragma unroll
        for (int kk = 0; kk < 32; kk++) {
            float av[8];
            #pragma unroll
            for (int ii = 0; ii < 8; ii++) av[ii] = As[(ty*8 + ii)*32 + kk];
            unsigned long long av2[4];
            #pragma unroll
            for (int q = 0; q < 4; q++) av2[q] = pack2(av[2*q], av[2*q+1]);
            #pragma unroll
            for (int jj = 0; jj < 5; jj++) {
                float bvv = Bs[(tx*5 + jj)*33 + kk];
                unsigned long long bv2 = pack2(bvv, bvv);
                #pragma unroll
                for (int q = 0; q < 4; q++) fma2(acc2[q][jj], av2[q], bv2);
            }
        }
        __syncthreads();
    }
    float* P = g_part + (size_t)ks*MR*GG;
    #pragma unroll
    for (int q = 0; q < 4; q++)
        #pragma unroll
        for (int jj = 0; jj < 5; jj++) {
            float lo, hi;
            unpack2(acc2[q][jj], lo, hi);
            P[(m0 + ty*8 + 2*q+0)*GG + tx*5 + jj] = lo;
            P[(m0 + ty*8 + 2*q+1)*GG + tx*5 + jj] = hi;
        }
}

__global__ void reduce_kernel() {
    int idx = blockIdx.x*256 + threadIdx.x;
    if (idx >= MR*GG) return;
    float s = g_pb[idx % GG];
    #pragma unroll
    for (int ks = 0; ks < KSPL; ks++) s += g_part[(size_t)ks*MR*GG + idx];
    g_xproj[idx] = s;
}

__device__ __forceinline__ float sigf(float x) { return 1.f / (1.f + __expf(-x)); }

__global__ void lstm2_kernel(const float* __restrict__ whh0,
                             const float* __restrict__ wih1, const float* __restrict__ whh1,
                             const float* __restrict__ bih1, const float* __restrict__ bhh1) {
    int b = blockIdx.x, tid = threadIdx.x;   // 96 threads
    __shared__ float h[20], gs[80], h0seq[LL*20];
    float w0r[20], w1i[20], w1h[20];
    float bias1 = 0.f;
    if (tid < 80) {
        #pragma unroll
        for (int jj = 0; jj < 20; jj++) {
            w0r[jj] = whh0[tid*20 + jj];
            w1i[jj] = wih1[tid*20 + jj];
            w1h[jj] = whh1[tid*20 + jj];
        }
        bias1 = bih1[tid] + bhh1[tid];
    }
    float cj = 0.f;
    if (tid < 20) h[tid] = 0.f;
    __syncthreads();
    for (int t = 0; t < LL; t++) {          // layer 0
        if (tid < 80) {
            float g = g_xproj[(b*LL + t)*GG + tid];
            float a0 = 0.f, a1 = 0.f, a2 = 0.f, a3 = 0.f;
            #pragma unroll
            for (int jj = 0; jj < 20; jj += 4) {
                a0 = fmaf(w0r[jj+0], h[jj+0], a0);
                a1 = fmaf(w0r[jj+1], h[jj+1], a1);
                a2 = fmaf(w0r[jj+2], h[jj+2], a2);
                a3 = fmaf(w0r[jj+3], h[jj+3], a3);
            }
            g += (a0 + a1) + (a2 + a3);
            gs[tid] = (tid >= 40 && tid < 60) ? tanhf(g) : sigf(g);
        }
        __syncthreads();
        if (tid < 20) {
            cj = fmaf(gs[20+tid], cj, gs[tid]*gs[40+tid]);
            float hj = gs[60+tid] * tanhf(cj);
            h[tid] = hj;
            h0seq[t*20 + tid] = hj;
        }
        __syncthreads();
    }
    cj = 0.f;
    if (tid < 20) h[tid] = 0.f;
    __syncthreads();
    for (int t = 0; t < LL; t++) {          // layer 1
        if (tid < 80) {
            float g = bias1;
            const float* xi = h0seq + t*20;
            float a0 = 0.f, a1 = 0.f, a2 = 0.f, a3 = 0.f;
            #pragma unroll
            for (int jj = 0; jj < 20; jj += 4) {
                a0 = fmaf(w1i[jj+0], xi[jj+0], a0);
                a1 = fmaf(w1i[jj+1], xi[jj+1], a1);
                a2 = fmaf(w1i[jj+2], xi[jj+2], a2);
                a3 = fmaf(w1i[jj+3], xi[jj+3], a3);
            }
            #pragma unroll
            for (int jj = 0; jj < 20; jj += 4) {
                a0 = fmaf(w1h[jj+0], h[jj+0], a0);
                a1 = fmaf(w1h[jj+1], h[jj+1], a1);
                a2 = fmaf(w1h[jj+2], h[jj+2], a2);
                a3 = fmaf(w1h[jj+3], h[jj+3], a3);
            }
            g += (a0 + a1) + (a2 + a3);
            gs[tid] = (tid >= 40 && tid < 60) ? tanhf(g) : sigf(g);
        }
        __syncthreads();
        if (tid < 20) {
            cj = fmaf(gs[20+tid], cj, gs[tid]*gs[40+tid]);
            float hj = gs[60+tid] * tanhf(cj);
            h[tid] = hj;
            g_o[(b*LL + t)*HH + tid] = hj;
        }
        __syncthreads();
    }
}

__global__ void final_kernel(const float* __restrict__ lw, const float* __restrict__ lb,
                             float* __restrict__ out) {
    int r = blockIdx.x*256 + threadIdx.x;
    if (r >= MR) return;
    float s = lb[0];
    #pragma unroll
    for (int hh = 0; hh < HH; hh++) {
        float v = g_o[r*HH + hh];
        v = (v >= 0.f) ? v : 0.01f*v;
        s = fmaf(v, lw[hh], s);
    }
    out[r] = s;
}

static void run_stage(const float* X, int KP, int KC,
                      const float* wih0, const float* whh0,
                      const float* bih0, const float* bhh0,
                      const float* wih1, const float* whh1,
                      const float* bih1, const float* bhh1,
                      bool first) {
    stats_kernel<<<(KP + 127)/128, 128>>>(X, KP);
    if (first)
        wfold_kernel<29, S3OFF1, 32, KP1><<<(GG*KP1 + 255)/256, 256>>>(wih0);
    else
        wfold_kernel<20, S3OFF2, 20, KP2><<<(GG*KP2 + 255)/256, 256>>>(wih0);
    projbias_kernel<<<GG, 256>>>(bih0, bhh0, KP);
    gemm_kernel<<<dim3(MR/128, KSPL), 256>>>(X, KP, KC);
    reduce_kernel<<<(MR*GG + 255)/256, 256>>>();
    lstm2_kernel<<<BB, 96>>>(whh0, wih1, whh1, bih1, bhh1);
}

extern "C" void kernel_launch(void* const* d_in, const int* in_sizes, int n_in,
                              void* d_out, int out_size) {
    const float* inp = (const float*)d_in[0];
    const float* aw1 = (const float*)d_in[1];
    const float* ab1 = (const float*)d_in[2];
    const float* aw2 = (const float*)d_in[3];
    const float* ab2 = (const float*)d_in[4];
    const float* p[24];
    for (int i = 0; i < 24; i++) p[i] = (const float*)d_in[5 + i];
    const float* lin_w = (const float*)d_in[29];
    const float* lin_b = (const float*)d_in[30];
    float* out = (float*)d_out;

    float* ga;  cudaGetSymbolAddress((void**)&ga,  g_a);
    float* gx1; cudaGetSymbolAddress((void**)&gx1, g_X1);
    float* gx2; cudaGetSymbolAddress((void**)&gx2, g_X2);
    float* go;  cudaGetSymbolAddress((void**)&go,  g_o);

    augment_kernel<<<MR, 64>>>(inp, aw1, ab1, aw2, ab2);
    sig_kernel<29, 32, S3OFF1, KP1, 8><<<dim3(8, BB), 128>>>(ga, 32, gx1);
    run_stage(gx1, KP1, 896, p[0], p[1], p[2], p[3], p[4], p[5], p[6], p[7], true);
    sig_kernel<20, 20, S3OFF2, KP2, 5><<<dim3(5, BB), 96>>>(go, HH, gx2);
    run_stage(gx2, KP2, 288, p[8], p[9], p[10], p[11], p[12], p[13], p[14], p[15], false);
    sig_kernel<20, 20, S3OFF2, KP2, 5><<<dim3(5, BB), 96>>>(go, HH, gx2);
    run_stage(gx2, KP2, 288, p[16], p[17], p[18], p[19], p[20], p[21], p[22], p[23], false);
    final_kernel<<<(MR + 255)/256, 256>>>(lin_w, lin_b, out);
}

// round 4
// speedup vs baseline: 2.4325x; 1.2131x over previous
#include <cuda_runtime.h>
#include <math.h>
#include <stdint.h>

#define BB 16
#define LL 128
#define HH 20
#define GG 80
#define MR (BB*LL)
#define KSPL 32
#define KP1 27808
#define S3OFF1 896
#define KP2 8432
#define S3OFF2 432

__device__ __align__(256) float g_a[MR*32];
__device__ __align__(256) float g_X1[(size_t)MR*KP1];
__device__ __align__(256) float g_X2[(size_t)MR*KP2];
__device__ float g_mean[KP1];
__device__ float g_invstd[KP1];
__device__ __align__(256) uint32_t g_Wrh[(size_t)GG*KP1];
__device__ __align__(256) uint32_t g_Wrl[(size_t)GG*KP1];
__device__ float g_pb[GG];
__device__ float g_xproj[MR*GG];
__device__ float g_part[(size_t)KSPL*MR*GG];
__device__ float g_o[MR*HH];

// ---------- tf32 helpers ----------
__device__ __forceinline__ void split_tf32(float v, uint32_t& hi, uint32_t& lo) {
    uint32_t h;
    asm("cvt.rna.tf32.f32 %0, %1;" : "=r"(h) : "f"(v));
    float r = v - __uint_as_float(h);
    uint32_t l;
    asm("cvt.rna.tf32.f32 %0, %1;" : "=r"(l) : "f"(r));
    hi = h; lo = l;
}
__device__ __forceinline__ void mma_tf32(float* c, const uint32_t* a, const uint32_t* b) {
    asm("mma.sync.aligned.m16n8k8.row.col.f32.tf32.tf32.f32 "
        "{%0,%1,%2,%3}, {%4,%5,%6,%7}, {%8,%9}, {%0,%1,%2,%3};"
        : "+f"(c[0]), "+f"(c[1]), "+f"(c[2]), "+f"(c[3])
        : "r"(a[0]), "r"(a[1]), "r"(a[2]), "r"(a[3]), "r"(b[0]), "r"(b[1]));
}

__global__ void augment_kernel(const float* __restrict__ inp,
                               const float* __restrict__ w1, const float* __restrict__ b1,
                               const float* __restrict__ w2, const float* __restrict__ b2) {
    int bl = blockIdx.x;
    int l = bl & (LL-1);
    int tid = threadIdx.x; // 64
    __shared__ float xin[20], hid[64], out8[8];
    if (tid < 20) xin[tid] = inp[bl*20 + tid];
    __syncthreads();
    {
        float a = b1[tid];
        const float* wr = w1 + tid*20;
        #pragma unroll
        for (int c = 0; c < 20; c++) a = fmaf(wr[c], xin[c], a);
        hid[tid] = fmaxf(a, 0.f);
    }
    __syncthreads();
    if (tid < 8) {
        float a = b2[tid];
        const float* wr = w2 + tid*64;
        #pragma unroll 8
        for (int c = 0; c < 64; c++) a = fmaf(wr[c], hid[c], a);
        out8[tid] = a;
    }
    __syncthreads();
    if (tid < 32) {
        float v = 0.f;
        if (tid == 0) v = (float)l * (1.0f/127.0f);
        else if (tid < 21) v = xin[tid-1];
        else if (tid < 29) v = out8[tid-21];
        g_a[bl*32 + tid] = v;
    }
}

// streamed depth-3 signature, split over pair-row groups.
template<int C, int RUN, int S3OFF, int KP, int NSPLIT>
__global__ void sig_kernel(const float* __restrict__ in, int instride,
                           float* __restrict__ X) {
    int g = blockIdx.x, b = blockIdx.y;
    int i0 = (g*C)/NSPLIT, i1 = ((g+1)*C)/NSPLIT;
    int tid = threadIdx.x;
    __shared__ __align__(16) float d[32];
    __shared__ float s1[32];
    int np = (i1 - i0) * C;
    bool act = tid < np;
    int i = i0 + tid / C, j = tid % C;
    int pg = i*C + j;
    float s2r = 0.f;
    float s3r[RUN];
    #pragma unroll
    for (int q = 0; q < RUN; q++) s3r[q] = 0.f;
    float prev = 0.f;
    if (tid < 32) { d[tid] = 0.f; s1[tid] = 0.f; }
    float nxt = (tid < C) ? in[(b*LL)*instride + tid] : 0.f;
    __syncthreads();
    for (int t = 0; t < LL; t++) {
        if (tid < 32) {
            float cur = (tid < C) ? nxt : 0.f;
            d[tid] = cur - prev;
            prev = cur;
        }
        __syncthreads();
        if (tid < C && t+1 < LL) nxt = in[(b*LL + t+1)*instride + tid];
        float* Xr = X + (size_t)(b*LL + t)*KP;
        if (act) {
            float di = d[i], dj = d[j], s1i = s1[i];
            float gam = fmaf(dj, fmaf(di, (1.f/6.f), 0.5f*s1i), s2r);
            s2r = fmaf(dj, fmaf(0.5f, di, s1i), s2r);
            const float4* d4 = (const float4*)d;
            float4* o4 = (float4*)(Xr + S3OFF + pg*RUN);
            #pragma unroll
            for (int q = 0; q < RUN/4; q++) {
                float4 dq = d4[q];
                s3r[4*q+0] = fmaf(gam, dq.x, s3r[4*q+0]);
                s3r[4*q+1] = fmaf(gam, dq.y, s3r[4*q+1]);
                s3r[4*q+2] = fmaf(gam, dq.z, s3r[4*q+2]);
                s3r[4*q+3] = fmaf(gam, dq.w, s3r[4*q+3]);
                o4[q] = make_float4(s3r[4*q+0], s3r[4*q+1], s3r[4*q+2], s3r[4*q+3]);
            }
            Xr[32 + pg] = s2r;
        }
        __syncthreads();
        if (tid < C) s1[tid] += d[tid];
        if (g == 0) {
            if (tid < 32) Xr[tid] = (tid < C) ? s1[tid] : 0.f;
            int gap0 = 32 + C*C;
            if (gap0 + tid < S3OFF) Xr[gap0 + tid] = 0.f;
        }
    }
}

__global__ void stats_kernel(const float* __restrict__ X, int KP) {
    int c = blockIdx.x*128 + threadIdx.x;
    if (c >= KP) return;
    const float* p = X + c;
    double sd = 0.0, qd = 0.0;
    for (int r = 0; r < MR; r += 8) {
        float v0 = p[(size_t)(r+0)*KP], v1 = p[(size_t)(r+1)*KP];
        float v2 = p[(size_t)(r+2)*KP], v3 = p[(size_t)(r+3)*KP];
        float v4 = p[(size_t)(r+4)*KP], v5 = p[(size_t)(r+5)*KP];
        float v6 = p[(size_t)(r+6)*KP], v7 = p[(size_t)(r+7)*KP];
        sd += (double)(((v0+v1)+(v2+v3)) + ((v4+v5)+(v6+v7)));
        qd += (double)(((v0*v0+v1*v1)+(v2*v2+v3*v3)) + ((v4*v4+v5*v5)+(v6*v6+v7*v7)));
    }
    double m = sd * (1.0/2048.0);
    double var = qd * (1.0/2048.0) - m*m;
    g_mean[c] = (float)m;
    g_invstd[c] = (float)(1.0 / sqrt(var + 1e-5));
}

template<int C, int S3OFF, int RUN, int KP>
__global__ void wfold_kernel(const float* __restrict__ W) {
    int idx = blockIdx.x*256 + threadIdx.x;
    if (idx >= GG*KP) return;
    int g = idx / KP, cp = idx - g*KP;
    const int CP = C*C;
    int c = -1;
    if (cp < 32) { if (cp < C) c = cp; }
    else if (cp < 32 + CP) c = C + (cp - 32);
    else if (cp >= S3OFF) {
        int r = cp - S3OFF; int p = r / RUN; int k = r - p*RUN;
        if (k < C) c = C + CP + p*C + k;
    }
    float v = 0.f;
    if (c >= 0) v = W[(size_t)g*(C + CP + CP*C) + c] * g_invstd[cp];
    uint32_t hi, lo;
    split_tf32(v, hi, lo);
    g_Wrh[idx] = hi;
    g_Wrl[idx] = lo;
}

__global__ void projbias_kernel(const float* __restrict__ bih, const float* __restrict__ bhh, int KP) {
    int g = blockIdx.x, tid = threadIdx.x;
    __shared__ double red[256];
    double s = 0.0;
    for (int c = tid; c < KP; c += 256) {
        float w = __uint_as_float(g_Wrh[(size_t)g*KP + c]) + __uint_as_float(g_Wrl[(size_t)g*KP + c]);
        s += (double)w * (double)g_mean[c];
    }
    red[tid] = s; __syncthreads();
    for (int st = 128; st > 0; st >>= 1) { if (tid < st) red[tid] += red[tid+st]; __syncthreads(); }
    if (tid == 0) g_pb[g] = bih[g] + bhh[g] - (float)red[0];
}

// tensor-core GEMM: X(2048 x KP) * Wr^T(KP x 80), tf32 2-term split, 3 mma passes.
// tile M=128, N=80, K=16; K-split over blockIdx.y (KP multiple of 16, KC multiple of 16)
__global__ void __launch_bounds__(256) gemm_tc(const float* __restrict__ X, int KP, int KC) {
    __shared__ __align__(16) uint32_t Ah[128*20];
    __shared__ __align__(16) uint32_t Al[128*20];
    __shared__ __align__(16) uint32_t Bh[80*20];
    __shared__ __align__(16) uint32_t Bl[80*20];
    int m0 = blockIdx.x * 128;
    int ks = blockIdx.y;
    int k0 = ks * KC;
    int kend = min(k0 + KC, KP);
    int tid = threadIdx.x;
    int warp = tid >> 5, lane = tid & 31;
    int wm = warp & 3, wn = warp >> 2;       // 4 x 2 warp grid
    int gq = lane >> 2, tig = lane & 3;
    float acc[2][5][4];
    #pragma unroll
    for (int mi = 0; mi < 2; mi++)
        #pragma unroll
        for (int ni = 0; ni < 5; ni++)
            #pragma unroll
            for (int q = 0; q < 4; q++) acc[mi][ni][q] = 0.f;

    for (int kb = k0; kb < kend; kb += 16) {
        // A tile: 128 rows x 16 k (fp32) -> split hi/lo
        #pragma unroll
        for (int u = 0; u < 2; u++) {
            int idx = tid + u*256;           // 0..511
            int row = idx >> 2, kq = (idx & 3) << 2;
            float4 v = *(const float4*)(X + (size_t)(m0 + row)*KP + kb + kq);
            uint4 h, l;
            split_tf32(v.x, h.x, l.x);
            split_tf32(v.y, h.y, l.y);
            split_tf32(v.z, h.z, l.z);
            split_tf32(v.w, h.w, l.w);
            *(uint4*)(Ah + row*20 + kq) = h;
            *(uint4*)(Al + row*20 + kq) = l;
        }
        // B tile: 80 rows(n) x 16 k, already split
        #pragma unroll
        for (int u = 0; u < 2; u++) {
            int idx = tid + u*256;
            if (idx < 320) {
                int row = idx >> 2, kq = (idx & 3) << 2;
                uint4 h = *(const uint4*)(g_Wrh + (size_t)row*KP + kb + kq);
                uint4 l = *(const uint4*)(g_Wrl + (size_t)row*KP + kb + kq);
                *(uint4*)(Bh + row*20 + kq) = h;
                *(uint4*)(Bl + row*20 + kq) = l;
            }
        }
        __syncthreads();
        #pragma unroll
        for (int k8 = 0; k8 < 2; k8++) {
            int kk = k8*8;
            uint32_t ah[2][4], al[2][4], bh[5][2], bl[5][2];
            #pragma unroll
            for (int mi = 0; mi < 2; mi++) {
                int rb = wm*32 + mi*16;
                ah[mi][0] = Ah[(rb+gq)*20 + kk + tig];
                ah[mi][1] = Ah[(rb+gq+8)*20 + kk + tig];
                ah[mi][2] = Ah[(rb+gq)*20 + kk + tig + 4];
                ah[mi][3] = Ah[(rb+gq+8)*20 + kk + tig + 4];
                al[mi][0] = Al[(rb+gq)*20 + kk + tig];
                al[mi][1] = Al[(rb+gq+8)*20 + kk + tig];
                al[mi][2] = Al[(rb+gq)*20 + kk + tig + 4];
                al[mi][3] = Al[(rb+gq+8)*20 + kk + tig + 4];
            }
            #pragma unroll
            for (int ni = 0; ni < 5; ni++) {
                int cb = wn*40 + ni*8;
                bh[ni][0] = Bh[(cb+gq)*20 + kk + tig];
                bh[ni][1] = Bh[(cb+gq)*20 + kk + tig + 4];
                bl[ni][0] = Bl[(cb+gq)*20 + kk + tig];
                bl[ni][1] = Bl[(cb+gq)*20 + kk + tig + 4];
            }
            #pragma unroll
            for (int mi = 0; mi < 2; mi++)
                #pragma unroll
                for (int ni = 0; ni < 5; ni++) {
                    mma_tf32(acc[mi][ni], ah[mi], bh[ni]);
                    mma_tf32(acc[mi][ni], al[mi], bh[ni]);
                    mma_tf32(acc[mi][ni], ah[mi], bl[ni]);
                }
        }
        __syncthreads();
    }
    float* P = g_part + (size_t)ks*MR*GG;
    #pragma unroll
    for (int mi = 0; mi < 2; mi++)
        #pragma unroll
        for (int ni = 0; ni < 5; ni++) {
            int m = m0 + wm*32 + mi*16;
            int n = wn*40 + ni*8 + 2*tig;
            *(float2*)&P[(m+gq)*GG + n]   = make_float2(acc[mi][ni][0], acc[mi][ni][1]);
            *(float2*)&P[(m+gq+8)*GG + n] = make_float2(acc[mi][ni][2], acc[mi][ni][3]);
        }
}

__global__ void reduce_kernel() {
    int idx = blockIdx.x*256 + threadIdx.x;
    if (idx >= MR*GG) return;
    float s = g_pb[idx % GG];
    #pragma unroll
    for (int ks = 0; ks < KSPL; ks++) s += g_part[(size_t)ks*MR*GG + idx];
    g_xproj[idx] = s;
}

__device__ __forceinline__ float sigf(float x) { return 1.f / (1.f + __expf(-x)); }

__global__ void lstm2_kernel(const float* __restrict__ whh0,
                             const float* __restrict__ wih1, const float* __restrict__ whh1,
                             const float* __restrict__ bih1, const float* __restrict__ bhh1) {
    int b = blockIdx.x, tid = threadIdx.x;   // 96 threads
    __shared__ float h[20], gs[80], h0seq[LL*20];
    float w0r[20], w1i[20], w1h[20];
    float bias1 = 0.f;
    if (tid < 80) {
        #pragma unroll
        for (int jj = 0; jj < 20; jj++) {
            w0r[jj] = whh0[tid*20 + jj];
            w1i[jj] = wih1[tid*20 + jj];
            w1h[jj] = whh1[tid*20 + jj];
        }
        bias1 = bih1[tid] + bhh1[tid];
    }
    float cj = 0.f;
    if (tid < 20) h[tid] = 0.f;
    __syncthreads();
    for (int t = 0; t < LL; t++) {          // layer 0
        if (tid < 80) {
            float g = g_xproj[(b*LL + t)*GG + tid];
            float a0 = 0.f, a1 = 0.f, a2 = 0.f, a3 = 0.f;
            #pragma unroll
            for (int jj = 0; jj < 20; jj += 4) {
                a0 = fmaf(w0r[jj+0], h[jj+0], a0);
                a1 = fmaf(w0r[jj+1], h[jj+1], a1);
                a2 = fmaf(w0r[jj+2], h[jj+2], a2);
                a3 = fmaf(w0r[jj+3], h[jj+3], a3);
            }
            g += (a0 + a1) + (a2 + a3);
            gs[tid] = (tid >= 40 && tid < 60) ? tanhf(g) : sigf(g);
        }
        __syncthreads();
        if (tid < 20) {
            cj = fmaf(gs[20+tid], cj, gs[tid]*gs[40+tid]);
            float hj = gs[60+tid] * tanhf(cj);
            h[tid] = hj;
            h0seq[t*20 + tid] = hj;
        }
        __syncthreads();
    }
    cj = 0.f;
    if (tid < 20) h[tid] = 0.f;
    __syncthreads();
    for (int t = 0; t < LL; t++) {          // layer 1
        if (tid < 80) {
            float g = bias1;
            const float* xi = h0seq + t*20;
            float a0 = 0.f, a1 = 0.f, a2 = 0.f, a3 = 0.f;
            #pragma unroll
            for (int jj = 0; jj < 20; jj += 4) {
                a0 = fmaf(w1i[jj+0], xi[jj+0], a0);
                a1 = fmaf(w1i[jj+1], xi[jj+1], a1);
                a2 = fmaf(w1i[jj+2], xi[jj+2], a2);
                a3 = fmaf(w1i[jj+3], xi[jj+3], a3);
            }
            #pragma unroll
            for (int jj = 0; jj < 20; jj += 4) {
                a0 = fmaf(w1h[jj+0], h[jj+0], a0);
                a1 = fmaf(w1h[jj+1], h[jj+1], a1);
                a2 = fmaf(w1h[jj+2], h[jj+2], a2);
                a3 = fmaf(w1h[jj+3], h[jj+3], a3);
            }
            g += (a0 + a1) + (a2 + a3);
            gs[tid] = (tid >= 40 && tid < 60) ? tanhf(g) : sigf(g);
        }
        __syncthreads();
        if (tid < 20) {
            cj = fmaf(gs[20+tid], cj, gs[tid]*gs[40+tid]);
            float hj = gs[60+tid] * tanhf(cj);
            h[tid] = hj;
            g_o[(b*LL + t)*HH + tid] = hj;
        }
        __syncthreads();
    }
}

__global__ void final_kernel(const float* __restrict__ lw, const float* __restrict__ lb,
                             float* __restrict__ out) {
    int r = blockIdx.x*256 + threadIdx.x;
    if (r >= MR) return;
    float s = lb[0];
    #pragma unroll
    for (int hh = 0; hh < HH; hh++) {
        float v = g_o[r*HH + hh];
        v = (v >= 0.f) ? v : 0.01f*v;
        s = fmaf(v, lw[hh], s);
    }
    out[r] = s;
}

static void run_stage(const float* X, int KP, int KC,
                      const float* wih0, const float* whh0,
                      const float* bih0, const float* bhh0,
                      const float* wih1, const float* whh1,
                      const float* bih1, const float* bhh1,
                      bool first) {
    stats_kernel<<<(KP + 127)/128, 128>>>(X, KP);
    if (first)
        wfold_kernel<29, S3OFF1, 32, KP1><<<(GG*KP1 + 255)/256, 256>>>(wih0);
    else
        wfold_kernel<20, S3OFF2, 20, KP2><<<(GG*KP2 + 255)/256, 256>>>(wih0);
    projbias_kernel<<<GG, 256>>>(bih0, bhh0, KP);
    gemm_tc<<<dim3(MR/128, KSPL), 256>>>(X, KP, KC);
    reduce_kernel<<<(MR*GG + 255)/256, 256>>>();
    lstm2_kernel<<<BB, 96>>>(whh0, wih1, whh1, bih1, bhh1);
}

extern "C" void kernel_launch(void* const* d_in, const int* in_sizes, int n_in,
                              void* d_out, int out_size) {
    const float* inp = (const float*)d_in[0];
    const float* aw1 = (const float*)d_in[1];
    const float* ab1 = (const float*)d_in[2];
    const float* aw2 = (const float*)d_in[3];
    const float* ab2 = (const float*)d_in[4];
    const float* p[24];
    for (int i = 0; i < 24; i++) p[i] = (const float*)d_in[5 + i];
    const float* lin_w = (const float*)d_in[29];
    const float* lin_b = (const float*)d_in[30];
    float* out = (float*)d_out;

    float* ga;  cudaGetSymbolAddress((void**)&ga,  g_a);
    float* gx1; cudaGetSymbolAddress((void**)&gx1, g_X1);
    float* gx2; cudaGetSymbolAddress((void**)&gx2, g_X2);
    float* go;  cudaGetSymbolAddress((void**)&go,  g_o);

    augment_kernel<<<MR, 64>>>(inp, aw1, ab1, aw2, ab2);
    sig_kernel<29, 32, S3OFF1, KP1, 8><<<dim3(8, BB), 128>>>(ga, 32, gx1);
    run_stage(gx1, KP1, 880, p[0], p[1], p[2], p[3], p[4], p[5], p[6], p[7], true);
    sig_kernel<20, 20, S3OFF2, KP2, 5><<<dim3(5, BB), 96>>>(go, HH, gx2);
    run_stage(gx2, KP2, 272, p[8], p[9], p[10], p[11], p[12], p[13], p[14], p[15], false);
    sig_kernel<20, 20, S3OFF2, KP2, 5><<<dim3(5, BB), 96>>>(go, HH, gx2);
    run_stage(gx2, KP2, 272, p[16], p[17], p[18], p[19], p[20], p[21], p[22], p[23], false);
    final_kernel<<<(MR + 255)/256, 256>>>(lin_w, lin_b, out);
}

// round 6
// speedup vs baseline: 2.8639x; 1.1773x over previous
#include <cuda_runtime.h>
#include <cuda_bf16.h>
#include <math.h>
#include <stdint.h>

#define BB 16
#define LL 128
#define HH 20
#define GG 80
#define MR (BB*LL)
#define KSPL 32
#define KP1 27808
#define S3OFF1 896
#define KP2 8432
#define S3OFF2 432

__device__ __align__(256) float g_a[MR*32];
__device__ __align__(256) float g_X1[(size_t)MR*KP1];
__device__ __align__(256) float g_X2[(size_t)MR*KP2];
__device__ float g_mean[KP1];
__device__ float g_invstd[KP1];
__device__ __align__(256) unsigned short g_Wh[(size_t)GG*KP1];
__device__ __align__(256) unsigned short g_Wl[(size_t)GG*KP1];
__device__ float g_pb[GG];
__device__ float g_xproj[MR*GG];
__device__ float g_part[(size_t)KSPL*MR*GG];
__device__ float g_o[MR*HH];

// ---------- bf16 split helpers ----------
__device__ __forceinline__ uint32_t bf2pack(float lo_elem, float hi_elem) {
    uint32_t w;
    asm("cvt.rn.bf16x2.f32 %0, %1, %2;" : "=r"(w) : "f"(hi_elem), "f"(lo_elem));
    return w;
}
__device__ __forceinline__ void split_pair(float vx, float vy, uint32_t& wh, uint32_t& wl) {
    wh = bf2pack(vx, vy);
    float hx = __uint_as_float(wh << 16);
    float hy = __uint_as_float(wh & 0xFFFF0000u);
    wl = bf2pack(vx - hx, vy - hy);
}
__device__ __forceinline__ void mma_bf16(float* c, const uint32_t* a, const uint32_t* b) {
    asm("mma.sync.aligned.m16n8k16.row.col.f32.bf16.bf16.f32 "
        "{%0,%1,%2,%3}, {%4,%5,%6,%7}, {%8,%9}, {%0,%1,%2,%3};"
        : "+f"(c[0]), "+f"(c[1]), "+f"(c[2]), "+f"(c[3])
        : "r"(a[0]), "r"(a[1]), "r"(a[2]), "r"(a[3]), "r"(b[0]), "r"(b[1]));
}

__global__ void augment_kernel(const float* __restrict__ inp,
                               const float* __restrict__ w1, const float* __restrict__ b1,
                               const float* __restrict__ w2, const float* __restrict__ b2) {
    int bl = blockIdx.x;
    int l = bl & (LL-1);
    int tid = threadIdx.x; // 64
    __shared__ float xin[20], hid[64], out8[8];
    if (tid < 20) xin[tid] = inp[bl*20 + tid];
    __syncthreads();
    {
        float a = b1[tid];
        const float* wr = w1 + tid*20;
        #pragma unroll
        for (int c = 0; c < 20; c++) a = fmaf(wr[c], xin[c], a);
        hid[tid] = fmaxf(a, 0.f);
    }
    __syncthreads();
    if (tid < 8) {
        float a = b2[tid];
        const float* wr = w2 + tid*64;
        #pragma unroll 8
        for (int c = 0; c < 64; c++) a = fmaf(wr[c], hid[c], a);
        out8[tid] = a;
    }
    __syncthreads();
    if (tid < 32) {
        float v = 0.f;
        if (tid == 0) v = (float)l * (1.0f/127.0f);
        else if (tid < 21) v = xin[tid-1];
        else if (tid < 29) v = out8[tid-21];
        g_a[bl*32 + tid] = v;
    }
}

// streamed depth-3 signature, split over pair-row groups.
template<int C, int RUN, int S3OFF, int KP, int NSPLIT>
__global__ void sig_kernel(const float* __restrict__ in, int instride,
                           float* __restrict__ X) {
    int g = blockIdx.x, b = blockIdx.y;
    int i0 = (g*C)/NSPLIT, i1 = ((g+1)*C)/NSPLIT;
    int tid = threadIdx.x;
    __shared__ __align__(16) float d[32];
    __shared__ float s1[32];
    int np = (i1 - i0) * C;
    bool act = tid < np;
    int i = i0 + tid / C, j = tid % C;
    int pg = i*C + j;
    float s2r = 0.f;
    float s3r[RUN];
    #pragma unroll
    for (int q = 0; q < RUN; q++) s3r[q] = 0.f;
    float prev = 0.f;
    if (tid < 32) { d[tid] = 0.f; s1[tid] = 0.f; }
    float nxt = (tid < C) ? in[(b*LL)*instride + tid] : 0.f;
    __syncthreads();
    for (int t = 0; t < LL; t++) {
        if (tid < 32) {
            float cur = (tid < C) ? nxt : 0.f;
            d[tid] = cur - prev;
            prev = cur;
        }
        __syncthreads();
        if (tid < C && t+1 < LL) nxt = in[(b*LL + t+1)*instride + tid];
        float* Xr = X + (size_t)(b*LL + t)*KP;
        if (act) {
            float di = d[i], dj = d[j], s1i = s1[i];
            float gam = fmaf(dj, fmaf(di, (1.f/6.f), 0.5f*s1i), s2r);
            s2r = fmaf(dj, fmaf(0.5f, di, s1i), s2r);
            const float4* d4 = (const float4*)d;
            float4* o4 = (float4*)(Xr + S3OFF + pg*RUN);
            #pragma unroll
            for (int q = 0; q < RUN/4; q++) {
                float4 dq = d4[q];
                s3r[4*q+0] = fmaf(gam, dq.x, s3r[4*q+0]);
                s3r[4*q+1] = fmaf(gam, dq.y, s3r[4*q+1]);
                s3r[4*q+2] = fmaf(gam, dq.z, s3r[4*q+2]);
                s3r[4*q+3] = fmaf(gam, dq.w, s3r[4*q+3]);
                o4[q] = make_float4(s3r[4*q+0], s3r[4*q+1], s3r[4*q+2], s3r[4*q+3]);
            }
            Xr[32 + pg] = s2r;
        }
        __syncthreads();
        if (tid < C) s1[tid] += d[tid];
        if (g == 0) {
            if (tid < 32) Xr[tid] = (tid < C) ? s1[tid] : 0.f;
            int gap0 = 32 + C*C;
            if (gap0 + tid < S3OFF) Xr[gap0 + tid] = 0.f;
        }
    }
}

__global__ void stats_kernel(const float* __restrict__ X, int KP) {
    int c = blockIdx.x*128 + threadIdx.x;
    if (c >= KP) return;
    const float* p = X + c;
    double sd = 0.0, qd = 0.0;
    for (int r = 0; r < MR; r += 8) {
        float v0 = p[(size_t)(r+0)*KP], v1 = p[(size_t)(r+1)*KP];
        float v2 = p[(size_t)(r+2)*KP], v3 = p[(size_t)(r+3)*KP];
        float v4 = p[(size_t)(r+4)*KP], v5 = p[(size_t)(r+5)*KP];
        float v6 = p[(size_t)(r+6)*KP], v7 = p[(size_t)(r+7)*KP];
        sd += (double)(((v0+v1)+(v2+v3)) + ((v4+v5)+(v6+v7)));
        qd += (double)(((v0*v0+v1*v1)+(v2*v2+v3*v3)) + ((v4*v4+v5*v5)+(v6*v6+v7*v7)));
    }
    double m = sd * (1.0/2048.0);
    double var = qd * (1.0/2048.0) - m*m;
    g_mean[c] = (float)m;
    g_invstd[c] = (float)(1.0 / sqrt(var + 1e-5));
}

template<int C, int S3OFF, int RUN, int KP>
__global__ void wfold_kernel(const float* __restrict__ W) {
    int idx = blockIdx.x*256 + threadIdx.x;
    if (idx >= GG*KP) return;
    int g = idx / KP, cp = idx - g*KP;
    const int CP = C*C;
    int c = -1;
    if (cp < 32) { if (cp < C) c = cp; }
    else if (cp < 32 + CP) c = C + (cp - 32);
    else if (cp >= S3OFF) {
        int r = cp - S3OFF; int p = r / RUN; int k = r - p*RUN;
        if (k < C) c = C + CP + p*C + k;
    }
    float v = 0.f;
    if (c >= 0) v = W[(size_t)g*(C + CP + CP*C) + c] * g_invstd[cp];
    unsigned short hb;
    asm("cvt.rn.bf16.f32 %0, %1;" : "=h"(hb) : "f"(v));
    float hf = __uint_as_float(((uint32_t)hb) << 16);
    unsigned short lb;
    asm("cvt.rn.bf16.f32 %0, %1;" : "=h"(lb) : "f"(v - hf));
    g_Wh[idx] = hb;
    g_Wl[idx] = lb;
}

__global__ void projbias_kernel(const float* __restrict__ bih, const float* __restrict__ bhh, int KP) {
    int g = blockIdx.x, tid = threadIdx.x;
    __shared__ double red[256];
    double s = 0.0;
    for (int c = tid; c < KP; c += 256) {
        float w = __uint_as_float(((uint32_t)g_Wh[(size_t)g*KP + c]) << 16)
                + __uint_as_float(((uint32_t)g_Wl[(size_t)g*KP + c]) << 16);
        s += (double)w * (double)g_mean[c];
    }
    red[tid] = s; __syncthreads();
    for (int st = 128; st > 0; st >>= 1) { if (tid < st) red[tid] += red[tid+st]; __syncthreads(); }
    if (tid == 0) g_pb[g] = bih[g] + bhh[g] - (float)red[0];
}

// tensor-core GEMM: X(2048 x KP) * W^T(KP x 80), bf16 2-term split, 3 mma passes,
// m16n8k16, software-pipelined global loads. tile M=128, N=80, K=16.
__global__ void __launch_bounds__(256) gemm_tc(const float* __restrict__ X, int KP, int KC) {
    __shared__ __align__(16) uint32_t Ah[128*12];
    __shared__ __align__(16) uint32_t Al[128*12];
    __shared__ __align__(16) uint32_t Bh[80*12];
    __shared__ __align__(16) uint32_t Bl[80*12];
    int m0 = blockIdx.x * 128;
    int ks = blockIdx.y;
    int k0 = ks * KC;
    int kend = min(k0 + KC, KP);
    int tid = threadIdx.x;
    int warp = tid >> 5, lane = tid & 31;
    int wm = warp & 3, wn = warp >> 2;       // 4 x 2 warp grid
    int gq = lane >> 2, tig = lane & 3;
    float acc[2][5][4];
    #pragma unroll
    for (int mi = 0; mi < 2; mi++)
        #pragma unroll
        for (int ni = 0; ni < 5; ni++)
            #pragma unroll
            for (int q = 0; q < 4; q++) acc[mi][ni][q] = 0.f;

    int arow0 = tid >> 2,        akq0 = (tid & 3) << 2;
    int arow1 = (tid+256) >> 2,  akq1 = akq0;
    int s0 = tid;
    int b0_lo = (s0 >= 160);  int b0r = (b0_lo ? s0-160 : s0) >> 1;  int b0s = s0 & 1;
    int s1v = tid + 256;      bool hasB1 = (s1v < 320);
    int b1r = (s1v-160) >> 1; int b1s = s1v & 1;

    if (k0 < kend) {
        float4 pa0, pa1; uint4 pb0, pb1;
        int kb = k0;
        pa0 = *(const float4*)(X + (size_t)(m0 + arow0)*KP + kb + akq0);
        pa1 = *(const float4*)(X + (size_t)(m0 + arow1)*KP + kb + akq1);
        {
            const unsigned short* bp0 = (b0_lo ? g_Wl : g_Wh) + (size_t)b0r*KP + kb + 8*b0s;
            pb0 = *(const uint4*)bp0;
            if (hasB1) pb1 = *(const uint4*)(g_Wl + (size_t)b1r*KP + kb + 8*b1s);
        }
        for (; kb < kend; kb += 16) {
            {
                uint32_t wh, wl;
                split_pair(pa0.x, pa0.y, wh, wl);
                uint32_t wh2, wl2;
                split_pair(pa0.z, pa0.w, wh2, wl2);
                *(uint2*)(Ah + arow0*12 + (akq0>>1)) = make_uint2(wh, wh2);
                *(uint2*)(Al + arow0*12 + (akq0>>1)) = make_uint2(wl, wl2);
                split_pair(pa1.x, pa1.y, wh, wl);
                split_pair(pa1.z, pa1.w, wh2, wl2);
                *(uint2*)(Ah + arow1*12 + (akq1>>1)) = make_uint2(wh, wh2);
                *(uint2*)(Al + arow1*12 + (akq1>>1)) = make_uint2(wl, wl2);
            }
            {
                uint32_t* buf = b0_lo ? Bl : Bh;
                *(uint4*)(buf + b0r*12 + 4*b0s) = pb0;
                if (hasB1) *(uint4*)(Bl + b1r*12 + 4*b1s) = pb1;
            }
            __syncthreads();
            if (kb + 16 < kend) {
                int kn = kb + 16;
                pa0 = *(const float4*)(X + (size_t)(m0 + arow0)*KP + kn + akq0);
                pa1 = *(const float4*)(X + (size_t)(m0 + arow1)*KP + kn + akq1);
                const unsigned short* bp0 = (b0_lo ? g_Wl : g_Wh) + (size_t)b0r*KP + kn + 8*b0s;
                pb0 = *(const uint4*)bp0;
                if (hasB1) pb1 = *(const uint4*)(g_Wl + (size_t)b1r*KP + kn + 8*b1s);
            }
            uint32_t ah[2][4], al[2][4], bh[5][2], bl[5][2];
            #pragma unroll
            for (int mi = 0; mi < 2; mi++) {
                int rb = wm*32 + mi*16;
                ah[mi][0] = Ah[(rb+gq)*12 + tig];
                ah[mi][1] = Ah[(rb+gq+8)*12 + tig];
                ah[mi][2] = Ah[(rb+gq)*12 + 4 + tig];
                ah[mi][3] = Ah[(rb+gq+8)*12 + 4 + tig];
                al[mi][0] = Al[(rb+gq)*12 + tig];
                al[mi][1] = Al[(rb+gq+8)*12 + tig];
                al[mi][2] = Al[(rb+gq)*12 + 4 + tig];
                al[mi][3] = Al[(rb+gq+8)*12 + 4 + tig];
            }
            #pragma unroll
            for (int ni = 0; ni < 5; ni++) {
                int cb = wn*40 + ni*8;
                bh[ni][0] = Bh[(cb+gq)*12 + tig];
                bh[ni][1] = Bh[(cb+gq)*12 + 4 + tig];
                bl[ni][0] = Bl[(cb+gq)*12 + tig];
                bl[ni][1] = Bl[(cb+gq)*12 + 4 + tig];
            }
            #pragma unroll
            for (int mi = 0; mi < 2; mi++)
                #pragma unroll
                for (int ni = 0; ni < 5; ni++) {
                    mma_bf16(acc[mi][ni], ah[mi], bh[ni]);
                    mma_bf16(acc[mi][ni], al[mi], bh[ni]);
                    mma_bf16(acc[mi][ni], ah[mi], bl[ni]);
                }
            __syncthreads();
        }
    }
    float* P = g_part + (size_t)ks*MR*GG;
    #pragma unroll
    for (int mi = 0; mi < 2; mi++)
        #pragma unroll
        for (int ni = 0; ni < 5; ni++) {
            int m = m0 + wm*32 + mi*16;
            int n = wn*40 + ni*8 + 2*tig;
            *(float2*)&P[(m+gq)*GG + n]   = make_float2(acc[mi][ni][0], acc[mi][ni][1]);
            *(float2*)&P[(m+gq+8)*GG + n] = make_float2(acc[mi][ni][2], acc[mi][ni][3]);
        }
}

__global__ void reduce_kernel() {
    int idx = blockIdx.x*256 + threadIdx.x;
    if (idx >= MR*GG) return;
    float s = g_pb[idx % GG];
    #pragma unroll
    for (int ks = 0; ks < KSPL; ks++) s += g_part[(size_t)ks*MR*GG + idx];
    g_xproj[idx] = s;
}

__device__ __forceinline__ float sigf(float x) { return 1.f / (1.f + __expf(-x)); }

__global__ void lstm2_kernel(const float* __restrict__ whh0,
                             const float* __restrict__ wih1, const float* __restrict__ whh1,
                             const float* __restrict__ bih1, const float* __restrict__ bhh1) {
    int b = blockIdx.x, tid = threadIdx.x;   // 96 threads
    __shared__ float h[20], gs[80], h0seq[LL*20];
    float w0r[20], w1i[20], w1h[20];
    float bias1 = 0.f;
    if (tid < 80) {
        #pragma unroll
        for (int jj = 0; jj < 20; jj++) {
            w0r[jj] = whh0[tid*20 + jj];
            w1i[jj] = wih1[tid*20 + jj];
            w1h[jj] = whh1[tid*20 + jj];
        }
        bias1 = bih1[tid] + bhh1[tid];
    }
    float cj = 0.f;
    if (tid < 20) h[tid] = 0.f;
    float xg = (tid < 80) ? g_xproj[(b*LL)*GG + tid] : 0.f;
    __syncthreads();
    for (int t = 0; t < LL; t++) {          // layer 0
        if (tid < 80) {
            float g = xg;
            float a0 = 0.f, a1 = 0.f, a2 = 0.f, a3 = 0.f;
            #pragma unroll
            for (int jj = 0; jj < 20; jj += 4) {
                a0 = fmaf(w0r[jj+0], h[jj+0], a0);
                a1 = fmaf(w0r[jj+1], h[jj+1], a1);
                a2 = fmaf(w0r[jj+2], h[jj+2], a2);
                a3 = fmaf(w0r[jj+3], h[jj+3], a3);
            }
            g += (a0 + a1) + (a2 + a3);
            gs[tid] = (tid >= 40 && tid < 60) ? tanhf(g) : sigf(g);
            if (t+1 < LL) xg = g_xproj[(b*LL + t+1)*GG + tid];
        }
        __syncthreads();
        if (tid < 20) {
            cj = fmaf(gs[20+tid], cj, gs[tid]*gs[40+tid]);
            float hj = gs[60+tid] * tanhf(cj);
            h[tid] = hj;
            h0seq[t*20 + tid] = hj;
        }
        __syncthreads();
    }
    cj = 0.f;
    if (tid < 20) h[tid] = 0.f;
    __syncthreads();
    for (int t = 0; t < LL; t++) {          // layer 1
        if (tid < 80) {
            float g = bias1;
            const float* xi = h0seq + t*20;
            float a0 = 0.f, a1 = 0.f, a2 = 0.f, a3 = 0.f;
            #pragma unroll
            for (int jj = 0; jj < 20; jj += 4) {
                a0 = fmaf(w1i[jj+0], xi[jj+0], a0);
                a1 = fmaf(w1i[jj+1], xi[jj+1], a1);
                a2 = fmaf(w1i[jj+2], xi[jj+2], a2);
                a3 = fmaf(w1i[jj+3], xi[jj+3], a3);
            }
            #pragma unroll
            for (int jj = 0; jj < 20; jj += 4) {
                a0 = fmaf(w1h[jj+0], h[jj+0], a0);
                a1 = fmaf(w1h[jj+1], h[jj+1], a1);
                a2 = fmaf(w1h[jj+2], h[jj+2], a2);
                a3 = fmaf(w1h[jj+3], h[jj+3], a3);
            }
            g += (a0 + a1) + (a2 + a3);
            gs[tid] = (tid >= 40 && tid < 60) ? tanhf(g) : sigf(g);
        }
        __syncthreads();
        if (tid < 20) {
            cj = fmaf(gs[20+tid], cj, gs[tid]*gs[40+tid]);
            float hj = gs[60+tid] * tanhf(cj);
            h[tid] = hj;
            g_o[(b*LL + t)*HH + tid] = hj;
        }
        __syncthreads();
    }
}

__global__ void final_kernel(const float* __restrict__ lw, const float* __restrict__ lb,
                             float* __restrict__ out) {
    int r = blockIdx.x*256 + threadIdx.x;
    if (r >= MR) return;
    float s = lb[0];
    #pragma unroll
    for (int hh = 0; hh < HH; hh++) {
        float v = g_o[r*HH + hh];
        v = (v >= 0.f) ? v : 0.01f*v;
        s = fmaf(v, lw[hh], s);
    }
    out[r] = s;
}

static void run_stage(const float* X, int KP, int KC,
                      const float* wih0, const float* whh0,
                      const float* bih0, const float* bhh0,
                      const float* wih1, const float* whh1,
                      const float* bih1, const float* bhh1,
                      bool first) {
    stats_kernel<<<(KP + 127)/128, 128>>>(X, KP);
    if (first)
        wfold_kernel<29, S3OFF1, 32, KP1><<<(GG*KP1 + 255)/256, 256>>>(wih0);
    else
        wfold_kernel<20, S3OFF2, 20, KP2><<<(GG*KP2 + 255)/256, 256>>>(wih0);
    projbias_kernel<<<GG, 256>>>(bih0, bhh0, KP);
    gemm_tc<<<dim3(MR/128, KSPL), 256>>>(X, KP, KC);
    reduce_kernel<<<(MR*GG + 255)/256, 256>>>();
    lstm2_kernel<<<BB, 96>>>(whh0, wih1, whh1, bih1, bhh1);
}

extern "C" void kernel_launch(void* const* d_in, const int* in_sizes, int n_in,
                              void* d_out, int out_size) {
    const float* inp = (const float*)d_in[0];
    const float* aw1 = (const float*)d_in[1];
    const float* ab1 = (const float*)d_in[2];
    const float* aw2 = (const float*)d_in[3];
    const float* ab2 = (const float*)d_in[4];
    const float* p[24];
    for (int i = 0; i < 24; i++) p[i] = (const float*)d_in[5 + i];
    const float* lin_w = (const float*)d_in[29];
    const float* lin_b = (const float*)d_in[30];
    float* out = (float*)d_out;

    float* ga;  cudaGetSymbolAddress((void**)&ga,  g_a);
    float* gx1; cudaGetSymbolAddress((void**)&gx1, g_X1);
    float* gx2; cudaGetSymbolAddress((void**)&gx2, g_X2);
    float* go;  cudaGetSymbolAddress((void**)&go,  g_o);

    augment_kernel<<<MR, 64>>>(inp, aw1, ab1, aw2, ab2);
    sig_kernel<29, 32, S3OFF1, KP1, 8><<<dim3(8, BB), 128>>>(ga, 32, gx1);
    run_stage(gx1, KP1, 880, p[0], p[1], p[2], p[3], p[4], p[5], p[6], p[7], true);
    sig_kernel<20, 20, S3OFF2, KP2, 5><<<dim3(5, BB), 96>>>(go, HH, gx2);
    run_stage(gx2, KP2, 272, p[8], p[9], p[10], p[11], p[12], p[13], p[14], p[15], false);
    sig_kernel<20, 20, S3OFF2, KP2, 5><<<dim3(5, BB), 96>>>(go, HH, gx2);
    run_stage(gx2, KP2, 272, p[16], p[17], p[18], p[19], p[20], p[21], p[22], p[23], false);
    final_kernel<<<(MR + 255)/256, 256>>>(lin_w, lin_b, out);
}

// round 7
// speedup vs baseline: 4.8886x; 1.7070x over previous
#include <cuda_runtime.h>
#include <cuda_bf16.h>
#include <math.h>
#include <stdint.h>

#define BB 16
#define LL 128
#define HH 20
#define GG 80
#define MR (BB*LL)
#define KSPL 32
#define KP1 27808
#define S3OFF1 896
#define KP2 8432
#define S3OFF2 432

__device__ __align__(256) float g_a[MR*32];
__device__ __align__(256) float g_X1[(size_t)MR*KP1];
__device__ __align__(256) float g_X2[(size_t)MR*KP2];
__device__ __align__(256) float2 g_sp[(size_t)BB*KP1];   // per-(b,channel) [sum, sumsq]
__device__ float g_mean[KP1];
__device__ float g_invstd[KP1];
__device__ __align__(256) unsigned short g_Wh[(size_t)GG*KP1];
__device__ __align__(256) unsigned short g_Wl[(size_t)GG*KP1];
__device__ float g_pb[GG];
__device__ float g_xproj[MR*GG];
__device__ float g_part[(size_t)KSPL*MR*GG];
__device__ float g_o[MR*HH];

// ---------- bf16 split helpers ----------
__device__ __forceinline__ uint32_t bf2pack(float lo_elem, float hi_elem) {
    uint32_t w;
    asm("cvt.rn.bf16x2.f32 %0, %1, %2;" : "=r"(w) : "f"(hi_elem), "f"(lo_elem));
    return w;
}
__device__ __forceinline__ void split_pair(float vx, float vy, uint32_t& wh, uint32_t& wl) {
    wh = bf2pack(vx, vy);
    float hx = __uint_as_float(wh << 16);
    float hy = __uint_as_float(wh & 0xFFFF0000u);
    wl = bf2pack(vx - hx, vy - hy);
}
__device__ __forceinline__ void mma_bf16(float* c, const uint32_t* a, const uint32_t* b) {
    asm("mma.sync.aligned.m16n8k16.row.col.f32.bf16.bf16.f32 "
        "{%0,%1,%2,%3}, {%4,%5,%6,%7}, {%8,%9}, {%0,%1,%2,%3};"
        : "+f"(c[0]), "+f"(c[1]), "+f"(c[2]), "+f"(c[3])
        : "r"(a[0]), "r"(a[1]), "r"(a[2]), "r"(a[3]), "r"(b[0]), "r"(b[1]));
}
__device__ __forceinline__ float tanh_ap(float x) {
    float y; asm("tanh.approx.f32 %0, %1;" : "=f"(y) : "f"(x)); return y;
}
__device__ __forceinline__ float sigf(float x) { return fmaf(0.5f, tanh_ap(0.5f*x), 0.5f); }

__global__ void augment_kernel(const float* __restrict__ inp,
                               const float* __restrict__ w1, const float* __restrict__ b1,
                               const float* __restrict__ w2, const float* __restrict__ b2) {
    int bl = blockIdx.x;
    int l = bl & (LL-1);
    int tid = threadIdx.x; // 64
    __shared__ float xin[20], hid[64], out8[8];
    if (tid < 20) xin[tid] = inp[bl*20 + tid];
    __syncthreads();
    {
        float a = b1[tid];
        const float* wr = w1 + tid*20;
        #pragma unroll
        for (int c = 0; c < 20; c++) a = fmaf(wr[c], xin[c], a);
        hid[tid] = fmaxf(a, 0.f);
    }
    __syncthreads();
    if (tid < 8) {
        float a = b2[tid];
        const float* wr = w2 + tid*64;
        #pragma unroll 8
        for (int c = 0; c < 64; c++) a = fmaf(wr[c], hid[c], a);
        out8[tid] = a;
    }
    __syncthreads();
    if (tid < 32) {
        float v = 0.f;
        if (tid == 0) v = (float)l * (1.0f/127.0f);
        else if (tid < 21) v = xin[tid-1];
        else if (tid < 29) v = out8[tid-21];
        g_a[bl*32 + tid] = v;
    }
}

// streamed depth-3 signature, split over pair-row groups; fused BN-stat partials.
template<int C, int RUN, int S3OFF, int KP, int NSPLIT>
__global__ void sig_kernel(const float* __restrict__ in, int instride,
                           float* __restrict__ X) {
    int g = blockIdx.x, b = blockIdx.y;
    int i0 = (g*C)/NSPLIT, i1 = ((g+1)*C)/NSPLIT;
    int tid = threadIdx.x;
    __shared__ __align__(16) float d[32];
    __shared__ float s1[32];
    int np = (i1 - i0) * C;
    bool act = tid < np;
    int i = i0 + tid / C, j = tid % C;
    int pg = i*C + j;
    float s2r = 0.f, sms2 = 0.f, sqs2 = 0.f;
    float s3r[RUN], sm3[RUN], sq3[RUN];
    #pragma unroll
    for (int q = 0; q < RUN; q++) { s3r[q] = 0.f; sm3[q] = 0.f; sq3[q] = 0.f; }
    float s1sum = 0.f, s1sq = 0.f;
    float prev = 0.f;
    if (tid < 32) { d[tid] = 0.f; s1[tid] = 0.f; }
    float nxt = (tid < C) ? in[(b*LL)*instride + tid] : 0.f;
    __syncthreads();
    for (int t = 0; t < LL; t++) {
        if (tid < 32) {
            float cur = (tid < C) ? nxt : 0.f;
            d[tid] = cur - prev;
            prev = cur;
        }
        __syncthreads();
        if (tid < C && t+1 < LL) nxt = in[(b*LL + t+1)*instride + tid];
        float* Xr = X + (size_t)(b*LL + t)*KP;
        if (act) {
            float di = d[i], dj = d[j], s1i = s1[i];
            float gam = fmaf(dj, fmaf(di, (1.f/6.f), 0.5f*s1i), s2r);
            s2r = fmaf(dj, fmaf(0.5f, di, s1i), s2r);
            sms2 += s2r; sqs2 = fmaf(s2r, s2r, sqs2);
            const float4* d4 = (const float4*)d;
            float4* o4 = (float4*)(Xr + S3OFF + pg*RUN);
            #pragma unroll
            for (int q = 0; q < RUN/4; q++) {
                float4 dq = d4[q];
                s3r[4*q+0] = fmaf(gam, dq.x, s3r[4*q+0]);
                s3r[4*q+1] = fmaf(gam, dq.y, s3r[4*q+1]);
                s3r[4*q+2] = fmaf(gam, dq.z, s3r[4*q+2]);
                s3r[4*q+3] = fmaf(gam, dq.w, s3r[4*q+3]);
                o4[q] = make_float4(s3r[4*q+0], s3r[4*q+1], s3r[4*q+2], s3r[4*q+3]);
                sm3[4*q+0] += s3r[4*q+0]; sq3[4*q+0] = fmaf(s3r[4*q+0], s3r[4*q+0], sq3[4*q+0]);
                sm3[4*q+1] += s3r[4*q+1]; sq3[4*q+1] = fmaf(s3r[4*q+1], s3r[4*q+1], sq3[4*q+1]);
                sm3[4*q+2] += s3r[4*q+2]; sq3[4*q+2] = fmaf(s3r[4*q+2], s3r[4*q+2], sq3[4*q+2]);
                sm3[4*q+3] += s3r[4*q+3]; sq3[4*q+3] = fmaf(s3r[4*q+3], s3r[4*q+3], sq3[4*q+3]);
            }
            Xr[32 + pg] = s2r;
        }
        __syncthreads();
        if (tid < C) s1[tid] += d[tid];
        if (g == 0) {
            float v = 0.f;
            if (tid < C) v = s1[tid];
            if (tid < 32) {
                Xr[tid] = v;
                s1sum += v; s1sq = fmaf(v, v, s1sq);
            }
            int gap0 = 32 + C*C;
            if (gap0 + tid < S3OFF) Xr[gap0 + tid] = 0.f;
        }
    }
    // write stat partials
    float2* SP = g_sp + (size_t)b*KP;
    if (act) {
        SP[32 + pg] = make_float2(sms2, sqs2);
        #pragma unroll
        for (int q = 0; q < RUN; q++)
            SP[S3OFF + pg*RUN + q] = make_float2(sm3[q], sq3[q]);
    }
    if (g == 0 && tid < 32) {
        SP[tid] = make_float2(s1sum, s1sq);
        int gap0 = 32 + C*C;
        if (gap0 + tid < S3OFF) SP[gap0 + tid] = make_float2(0.f, 0.f);
    }
}

__global__ void finalize_kernel(int KP) {
    int c = blockIdx.x*128 + threadIdx.x;
    if (c >= KP) return;
    double s = 0.0, q = 0.0;
    #pragma unroll
    for (int b = 0; b < BB; b++) {
        float2 v = g_sp[(size_t)b*KP + c];
        s += (double)v.x; q += (double)v.y;
    }
    double m = s * (1.0/2048.0);
    double var = q * (1.0/2048.0) - m*m;
    g_mean[c] = (float)m;
    g_invstd[c] = (float)(1.0 / sqrt(var + 1e-5));
}

template<int C, int S3OFF, int RUN, int KP>
__global__ void wfold_kernel(const float* __restrict__ W) {
    int idx = blockIdx.x*256 + threadIdx.x;
    if (idx >= GG*KP) return;
    int g = idx / KP, cp = idx - g*KP;
    const int CP = C*C;
    int c = -1;
    if (cp < 32) { if (cp < C) c = cp; }
    else if (cp < 32 + CP) c = C + (cp - 32);
    else if (cp >= S3OFF) {
        int r = cp - S3OFF; int p = r / RUN; int k = r - p*RUN;
        if (k < C) c = C + CP + p*C + k;
    }
    float v = 0.f;
    if (c >= 0) v = W[(size_t)g*(C + CP + CP*C) + c] * g_invstd[cp];
    unsigned short hb;
    asm("cvt.rn.bf16.f32 %0, %1;" : "=h"(hb) : "f"(v));
    float hf = __uint_as_float(((uint32_t)hb) << 16);
    unsigned short lb;
    asm("cvt.rn.bf16.f32 %0, %1;" : "=h"(lb) : "f"(v - hf));
    g_Wh[idx] = hb;
    g_Wl[idx] = lb;
}

__global__ void projbias_kernel(const float* __restrict__ bih, const float* __restrict__ bhh, int KP) {
    int g = blockIdx.x, tid = threadIdx.x;
    __shared__ double red[256];
    double s = 0.0;
    for (int c = tid; c < KP; c += 256) {
        float w = __uint_as_float(((uint32_t)g_Wh[(size_t)g*KP + c]) << 16)
                + __uint_as_float(((uint32_t)g_Wl[(size_t)g*KP + c]) << 16);
        s += (double)w * (double)g_mean[c];
    }
    red[tid] = s; __syncthreads();
    for (int st = 128; st > 0; st >>= 1) { if (tid < st) red[tid] += red[tid+st]; __syncthreads(); }
    if (tid == 0) g_pb[g] = bih[g] + bhh[g] - (float)red[0];
}

// tensor-core GEMM: X(2048 x KP) * W^T(KP x 80), bf16 2-term split, 3 mma passes,
// m16n8k16, software-pipelined global loads. tile M=128, N=80, K=16.
__global__ void __launch_bounds__(256) gemm_tc(const float* __restrict__ X, int KP, int KC) {
    __shared__ __align__(16) uint32_t Ah[128*12];
    __shared__ __align__(16) uint32_t Al[128*12];
    __shared__ __align__(16) uint32_t Bh[80*12];
    __shared__ __align__(16) uint32_t Bl[80*12];
    int m0 = blockIdx.x * 128;
    int ks = blockIdx.y;
    int k0 = ks * KC;
    int kend = min(k0 + KC, KP);
    int tid = threadIdx.x;
    int warp = tid >> 5, lane = tid & 31;
    int wm = warp & 3, wn = warp >> 2;       // 4 x 2 warp grid
    int gq = lane >> 2, tig = lane & 3;
    float acc[2][5][4];
    #pragma unroll
    for (int mi = 0; mi < 2; mi++)
        #pragma unroll
        for (int ni = 0; ni < 5; ni++)
            #pragma unroll
            for (int q = 0; q < 4; q++) acc[mi][ni][q] = 0.f;

    int arow0 = tid >> 2,        akq0 = (tid & 3) << 2;
    int arow1 = (tid+256) >> 2,  akq1 = akq0;
    int s0 = tid;
    int b0_lo = (s0 >= 160);  int b0r = (b0_lo ? s0-160 : s0) >> 1;  int b0s = s0 & 1;
    int s1v = tid + 256;      bool hasB1 = (s1v < 320);
    int b1r = (s1v-160) >> 1; int b1s = s1v & 1;

    if (k0 < kend) {
        float4 pa0, pa1; uint4 pb0, pb1;
        int kb = k0;
        pa0 = *(const float4*)(X + (size_t)(m0 + arow0)*KP + kb + akq0);
        pa1 = *(const float4*)(X + (size_t)(m0 + arow1)*KP + kb + akq1);
        {
            const unsigned short* bp0 = (b0_lo ? g_Wl : g_Wh) + (size_t)b0r*KP + kb + 8*b0s;
            pb0 = *(const uint4*)bp0;
            if (hasB1) pb1 = *(const uint4*)(g_Wl + (size_t)b1r*KP + kb + 8*b1s);
        }
        for (; kb < kend; kb += 16) {
            {
                uint32_t wh, wl;
                split_pair(pa0.x, pa0.y, wh, wl);
                uint32_t wh2, wl2;
                split_pair(pa0.z, pa0.w, wh2, wl2);
                *(uint2*)(Ah + arow0*12 + (akq0>>1)) = make_uint2(wh, wh2);
                *(uint2*)(Al + arow0*12 + (akq0>>1)) = make_uint2(wl, wl2);
                split_pair(pa1.x, pa1.y, wh, wl);
                split_pair(pa1.z, pa1.w, wh2, wl2);
                *(uint2*)(Ah + arow1*12 + (akq1>>1)) = make_uint2(wh, wh2);
                *(uint2*)(Al + arow1*12 + (akq1>>1)) = make_uint2(wl, wl2);
            }
            {
                uint32_t* buf = b0_lo ? Bl : Bh;
                *(uint4*)(buf + b0r*12 + 4*b0s) = pb0;
                if (hasB1) *(uint4*)(Bl + b1r*12 + 4*b1s) = pb1;
            }
            __syncthreads();
            if (kb + 16 < kend) {
                int kn = kb + 16;
                pa0 = *(const float4*)(X + (size_t)(m0 + arow0)*KP + kn + akq0);
                pa1 = *(const float4*)(X + (size_t)(m0 + arow1)*KP + kn + akq1);
                const unsigned short* bp0 = (b0_lo ? g_Wl : g_Wh) + (size_t)b0r*KP + kn + 8*b0s;
                pb0 = *(const uint4*)bp0;
                if (hasB1) pb1 = *(const uint4*)(g_Wl + (size_t)b1r*KP + kn + 8*b1s);
            }
            uint32_t ah[2][4], al[2][4], bh[5][2], bl[5][2];
            #pragma unroll
            for (int mi = 0; mi < 2; mi++) {
                int rb = wm*32 + mi*16;
                ah[mi][0] = Ah[(rb+gq)*12 + tig];
                ah[mi][1] = Ah[(rb+gq+8)*12 + tig];
                ah[mi][2] = Ah[(rb+gq)*12 + 4 + tig];
                ah[mi][3] = Ah[(rb+gq+8)*12 + 4 + tig];
                al[mi][0] = Al[(rb+gq)*12 + tig];
                al[mi][1] = Al[(rb+gq+8)*12 + tig];
                al[mi][2] = Al[(rb+gq)*12 + 4 + tig];
                al[mi][3] = Al[(rb+gq+8)*12 + 4 + tig];
            }
            #pragma unroll
            for (int ni = 0; ni < 5; ni++) {
                int cb = wn*40 + ni*8;
                bh[ni][0] = Bh[(cb+gq)*12 + tig];
                bh[ni][1] = Bh[(cb+gq)*12 + 4 + tig];
                bl[ni][0] = Bl[(cb+gq)*12 + tig];
                bl[ni][1] = Bl[(cb+gq)*12 + 4 + tig];
            }
            #pragma unroll
            for (int mi = 0; mi < 2; mi++)
                #pragma unroll
                for (int ni = 0; ni < 5; ni++) {
                    mma_bf16(acc[mi][ni], ah[mi], bh[ni]);
                    mma_bf16(acc[mi][ni], al[mi], bh[ni]);
                    mma_bf16(acc[mi][ni], ah[mi], bl[ni]);
                }
            __syncthreads();
        }
    }
    float* P = g_part + (size_t)ks*MR*GG;
    #pragma unroll
    for (int mi = 0; mi < 2; mi++)
        #pragma unroll
        for (int ni = 0; ni < 5; ni++) {
            int m = m0 + wm*32 + mi*16;
            int n = wn*40 + ni*8 + 2*tig;
            *(float2*)&P[(m+gq)*GG + n]   = make_float2(acc[mi][ni][0], acc[mi][ni][1]);
            *(float2*)&P[(m+gq+8)*GG + n] = make_float2(acc[mi][ni][2], acc[mi][ni][3]);
        }
}

__global__ void reduce_kernel() {
    int idx = blockIdx.x*256 + threadIdx.x;
    if (idx >= MR*GG) return;
    float s = g_pb[idx % GG];
    #pragma unroll
    for (int ks = 0; ks < KSPL; ks++) s += g_part[(size_t)ks*MR*GG + idx];
    g_xproj[idx] = s;
}

__global__ void lstm2_kernel(const float* __restrict__ whh0,
                             const float* __restrict__ wih1, const float* __restrict__ whh1,
                             const float* __restrict__ bih1, const float* __restrict__ bhh1) {
    int b = blockIdx.x, tid = threadIdx.x;   // 96 threads
    __shared__ float h[20], gs[80], h0seq[LL*20];
    float w0r[20], w1i[20], w1h[20];
    float bias1 = 0.f;
    if (tid < 80) {
        #pragma unroll
        for (int jj = 0; jj < 20; jj++) {
            w0r[jj] = whh0[tid*20 + jj];
            w1i[jj] = wih1[tid*20 + jj];
            w1h[jj] = whh1[tid*20 + jj];
        }
        bias1 = bih1[tid] + bhh1[tid];
    }
    float cj = 0.f;
    if (tid < 20) h[tid] = 0.f;
    float xg = (tid < 80) ? g_xproj[(b*LL)*GG + tid] : 0.f;
    __syncthreads();
    for (int t = 0; t < LL; t++) {          // layer 0
        if (tid < 80) {
            float g = xg;
            float a0 = 0.f, a1 = 0.f, a2 = 0.f, a3 = 0.f;
            #pragma unroll
            for (int jj = 0; jj < 20; jj += 4) {
                a0 = fmaf(w0r[jj+0], h[jj+0], a0);
                a1 = fmaf(w0r[jj+1], h[jj+1], a1);
                a2 = fmaf(w0r[jj+2], h[jj+2], a2);
                a3 = fmaf(w0r[jj+3], h[jj+3], a3);
            }
            g += (a0 + a1) + (a2 + a3);
            gs[tid] = (tid >= 40 && tid < 60) ? tanh_ap(g) : sigf(g);
            if (t+1 < LL) xg = g_xproj[(b*LL + t+1)*GG + tid];
        }
        __syncthreads();
        if (tid < 20) {
            cj = fmaf(gs[20+tid], cj, gs[tid]*gs[40+tid]);
            float hj = gs[60+tid] * tanh_ap(cj);
            h[tid] = hj;
            h0seq[t*20 + tid] = hj;
        }
        __syncthreads();
    }
    cj = 0.f;
    if (tid < 20) h[tid] = 0.f;
    __syncthreads();
    for (int t = 0; t < LL; t++) {          // layer 1
        if (tid < 80) {
            float g = bias1;
            const float* xi = h0seq + t*20;
            float a0 = 0.f, a1 = 0.f, a2 = 0.f, a3 = 0.f;
            #pragma unroll
            for (int jj = 0; jj < 20; jj += 4) {
                a0 = fmaf(w1i[jj+0], xi[jj+0], a0);
                a1 = fmaf(w1i[jj+1], xi[jj+1], a1);
                a2 = fmaf(w1i[jj+2], xi[jj+2], a2);
                a3 = fmaf(w1i[jj+3], xi[jj+3], a3);
            }
            #pragma unroll
            for (int jj = 0; jj < 20; jj += 4) {
                a0 = fmaf(w1h[jj+0], h[jj+0], a0);
                a1 = fmaf(w1h[jj+1], h[jj+1], a1);
                a2 = fmaf(w1h[jj+2], h[jj+2], a2);
                a3 = fmaf(w1h[jj+3], h[jj+3], a3);
            }
            g += (a0 + a1) + (a2 + a3);
            gs[tid] = (tid >= 40 && tid < 60) ? tanh_ap(g) : sigf(g);
        }
        __syncthreads();
        if (tid < 20) {
            cj = fmaf(gs[20+tid], cj, gs[tid]*gs[40+tid]);
            float hj = gs[60+tid] * tanh_ap(cj);
            h[tid] = hj;
            g_o[(b*LL + t)*HH + tid] = hj;
        }
        __syncthreads();
    }
}

__global__ void final_kernel(const float* __restrict__ lw, const float* __restrict__ lb,
                             float* __restrict__ out) {
    int r = blockIdx.x*256 + threadIdx.x;
    if (r >= MR) return;
    float s = lb[0];
    #pragma unroll
    for (int hh = 0; hh < HH; hh++) {
        float v = g_o[r*HH + hh];
        v = (v >= 0.f) ? v : 0.01f*v;
        s = fmaf(v, lw[hh], s);
    }
    out[r] = s;
}

static void run_stage(const float* X, int KP, int KC,
                      const float* wih0, const float* whh0,
                      const float* bih0, const float* bhh0,
                      const float* wih1, const float* whh1,
                      const float* bih1, const float* bhh1,
                      bool first) {
    finalize_kernel<<<(KP + 127)/128, 128>>>(KP);
    if (first)
        wfold_kernel<29, S3OFF1, 32, KP1><<<(GG*KP1 + 255)/256, 256>>>(wih0);
    else
        wfold_kernel<20, S3OFF2, 20, KP2><<<(GG*KP2 + 255)/256, 256>>>(wih0);
    projbias_kernel<<<GG, 256>>>(bih0, bhh0, KP);
    gemm_tc<<<dim3(MR/128, KSPL), 256>>>(X, KP, KC);
    reduce_kernel<<<(MR*GG + 255)/256, 256>>>();
    lstm2_kernel<<<BB, 96>>>(whh0, wih1, whh1, bih1, bhh1);
}

extern "C" void kernel_launch(void* const* d_in, const int* in_sizes, int n_in,
                              void* d_out, int out_size) {
    const float* inp = (const float*)d_in[0];
    const float* aw1 = (const float*)d_in[1];
    const float* ab1 = (const float*)d_in[2];
    const float* aw2 = (const float*)d_in[3];
    const float* ab2 = (const float*)d_in[4];
    const float* p[24];
    for (int i = 0; i < 24; i++) p[i] = (const float*)d_in[5 + i];
    const float* lin_w = (const float*)d_in[29];
    const float* lin_b = (const float*)d_in[30];
    float* out = (float*)d_out;

    float* ga;  cudaGetSymbolAddress((void**)&ga,  g_a);
    float* gx1; cudaGetSymbolAddress((void**)&gx1, g_X1);
    float* gx2; cudaGetSymbolAddress((void**)&gx2, g_X2);
    float* go;  cudaGetSymbolAddress((void**)&go,  g_o);

    augment_kernel<<<MR, 64>>>(inp, aw1, ab1, aw2, ab2);
    sig_kernel<29, 32, S3OFF1, KP1, 8><<<dim3(8, BB), 128>>>(ga, 32, gx1);
    run_stage(gx1, KP1, 880, p[0], p[1], p[2], p[3], p[4], p[5], p[6], p[7], true);
    sig_kernel<20, 20, S3OFF2, KP2, 5><<<dim3(5, BB), 96>>>(go, HH, gx2);
    run_stage(gx2, KP2, 272, p[8], p[9], p[10], p[11], p[12], p[13], p[14], p[15], false);
    sig_kernel<20, 20, S3OFF2, KP2, 5><<<dim3(5, BB), 96>>>(go, HH, gx2);
    run_stage(gx2, KP2, 272, p[16], p[17], p[18], p[19], p[20], p[21], p[22], p[23], false);
    final_kernel<<<(MR + 255)/256, 256>>>(lin_w, lin_b, out);
}